// round 5
// baseline (speedup 1.0000x reference)
#include <cuda_runtime.h>
#include <cuda_bf16.h>
#include <math.h>
#include <stdint.h>

#define NMAX 100000
#define EMAX 1600000
#define ETMAX (EMAX + NMAX)
#define SCAN_CHUNK 512

// ---------------- scratch (device globals; no allocation allowed) ----------------
__device__ __nv_bfloat16 g_h1b[NMAX * 128];  // layer1 features, bf16 (25.6 MB)
__device__ float4 g_as1[NMAX];               // alpha_src layer1 (4 heads)
__device__ float4 g_ad1[NMAX];               // alpha_dst layer1
__device__ float  g_h2[NMAX * 8];
__device__ float  g_as2[NMAX];
__device__ float  g_ad2[NMAX];
// CSR scratch
__device__ int    g_deg[NMAX];
__device__ int    g_rowstart[NMAX + 1];
__device__ int    g_fill[NMAX];
__device__ int    g_srcs[ETMAX];
__device__ int    g_csum[(NMAX + SCAN_CHUNK - 1) / SCAN_CHUNK];
__device__ int    g_coff[(NMAX + SCAN_CHUNK - 1) / SCAN_CHUNK];

// ---------------- helpers ----------------
__device__ __forceinline__ float lrelu(float v) { return v > 0.f ? v : 0.2f * v; }
__device__ __forceinline__ float eluf(float v)  { return v > 0.f ? v : (__expf(v) - 1.f); }
__device__ __forceinline__ float wmaxf(float v) {
#pragma unroll
    for (int o = 16; o; o >>= 1) v = fmaxf(v, __shfl_xor_sync(0xffffffffu, v, o));
    return v;
}
__device__ __forceinline__ float wsumf(float v) {
#pragma unroll
    for (int o = 16; o; o >>= 1) v += __shfl_xor_sync(0xffffffffu, v, o);
    return v;
}
__device__ __forceinline__ uint32_t f2tf32(float f) {
    uint32_t r; asm("cvt.rna.tf32.f32 %0, %1;" : "=r"(r) : "f"(f)); return r;
}
__device__ __forceinline__ void mma_tf32(float& d0, float& d1, float& d2, float& d3,
                                         uint32_t a0, uint32_t a1, uint32_t a2, uint32_t a3,
                                         uint32_t b0, uint32_t b1) {
    asm("mma.sync.aligned.m16n8k8.row.col.f32.tf32.tf32.f32 "
        "{%0,%1,%2,%3}, {%4,%5,%6,%7}, {%8,%9}, {%0,%1,%2,%3};"
        : "+f"(d0), "+f"(d1), "+f"(d2), "+f"(d3)
        : "r"(a0), "r"(a1), "r"(a2), "r"(a3), "r"(b0), "r"(b1));
}

// ---------------- CSR build ----------------
__global__ void zero_deg_kernel(int N) {
    int i = blockIdx.x * blockDim.x + threadIdx.x;
    if (i < N) g_deg[i] = 0;
}

__global__ void count_kernel(const int* __restrict__ ei, int E, int Etot) {
    int idx = blockIdx.x * blockDim.x + threadIdx.x;
    if (idx >= Etot) return;
    int dst = (idx < E) ? ei[E + idx] : (idx - E);
    atomicAdd(&g_deg[dst], 1);
}

__global__ void scan1_kernel(int N) {
    __shared__ int sh[SCAN_CHUNK];
    int t = threadIdx.x;
    int i = blockIdx.x * SCAN_CHUNK + t;
    sh[t] = (i < N) ? g_deg[i] : 0;
    __syncthreads();
#pragma unroll
    for (int s = SCAN_CHUNK / 2; s > 0; s >>= 1) {
        if (t < s) sh[t] += sh[t + s];
        __syncthreads();
    }
    if (t == 0) g_csum[blockIdx.x] = sh[0];
}

__global__ void scan2_kernel(int nch) {
    __shared__ int sh[SCAN_CHUNK];
    int t = threadIdx.x;
    int v = (t < nch) ? g_csum[t] : 0;
    sh[t] = v;
    __syncthreads();
#pragma unroll
    for (int off = 1; off < SCAN_CHUNK; off <<= 1) {
        int add = (t >= off) ? sh[t - off] : 0;
        __syncthreads();
        sh[t] += add;
        __syncthreads();
    }
    if (t < nch) g_coff[t] = sh[t] - v;
}

__global__ void scan3_kernel(int N, int Etot) {
    __shared__ int sh[SCAN_CHUNK];
    int t = threadIdx.x;
    int i = blockIdx.x * SCAN_CHUNK + t;
    int v = (i < N) ? g_deg[i] : 0;
    sh[t] = v;
    __syncthreads();
#pragma unroll
    for (int off = 1; off < SCAN_CHUNK; off <<= 1) {
        int add = (t >= off) ? sh[t - off] : 0;
        __syncthreads();
        sh[t] += add;
        __syncthreads();
    }
    if (i < N) {
        int excl = sh[t] - v + g_coff[blockIdx.x];
        g_rowstart[i] = excl;
        g_fill[i] = excl;
    }
    if (blockIdx.x == 0 && t == 0) g_rowstart[N] = Etot;
}

__global__ void fill_kernel(const int* __restrict__ ei, int E, int Etot) {
    int idx = blockIdx.x * blockDim.x + threadIdx.x;
    if (idx >= Etot) return;
    int src, dst;
    if (idx < E) { src = ei[idx]; dst = ei[E + idx]; } else { src = dst = idx - E; }
    int p = atomicAdd(&g_fill[dst], 1);
    g_srcs[p] = src;
}

// ---------------- layer1 GEMM (tf32 tensor cores) + fused alpha epilogue ----------------
__global__ __launch_bounds__(512) void gemm1_kernel(
    const float* __restrict__ x, const float* __restrict__ W,
    const float* __restrict__ asrc, const float* __restrict__ adst, int N) {
    extern __shared__ float sm[];
    float* xs = sm;               // 256*132
    float* wk = sm + 256 * 132;   // 128*136
    int tid = threadIdx.x;
    int base = blockIdx.x * 256;

    for (int i = tid; i < 4096; i += 512) {
        int k = i >> 5, c4 = i & 31;
        float4 v = ((const float4*)W)[i];
        float4 o;
        o.x = __uint_as_float(f2tf32(v.x));
        o.y = __uint_as_float(f2tf32(v.y));
        o.z = __uint_as_float(f2tf32(v.z));
        o.w = __uint_as_float(f2tf32(v.w));
        *(float4*)&wk[k * 136 + c4 * 4] = o;
    }
    for (int i = tid; i < 8192; i += 512) {
        int r = i >> 5, c4 = i & 31;
        int gr = base + r;
        float4 v = make_float4(0.f, 0.f, 0.f, 0.f);
        if (gr < N) v = ((const float4*)x)[gr * 32 + c4];
        float4 o;
        o.x = __uint_as_float(f2tf32(v.x));
        o.y = __uint_as_float(f2tf32(v.y));
        o.z = __uint_as_float(f2tf32(v.z));
        o.w = __uint_as_float(f2tf32(v.w));
        *(float4*)&xs[r * 132 + c4 * 4] = o;
    }
    __syncthreads();

    int w = tid >> 5, lane = tid & 31;
    int tg = lane & 3, grp = lane >> 2;
    int r0 = w * 16;

    float acc[16][4];
#pragma unroll
    for (int j = 0; j < 16; j++)
#pragma unroll
        for (int q = 0; q < 4; q++) acc[j][q] = 0.f;

#pragma unroll 4
    for (int ks = 0; ks < 16; ks++) {
        int k0 = ks * 8;
        const float* ax = xs + (r0 + grp) * 132 + k0 + tg;
        uint32_t a0 = __float_as_uint(ax[0]);
        uint32_t a1 = __float_as_uint(ax[8 * 132]);
        uint32_t a2 = __float_as_uint(ax[4]);
        uint32_t a3 = __float_as_uint(ax[8 * 132 + 4]);
        const float* bx = wk + (k0 + tg) * 136 + grp;
#pragma unroll
        for (int j = 0; j < 16; j++) {
            uint32_t b0 = __float_as_uint(bx[8 * j]);
            uint32_t b1 = __float_as_uint(bx[4 * 136 + 8 * j]);
            mma_tf32(acc[j][0], acc[j][1], acc[j][2], acc[j][3], a0, a1, a2, a3, b0, b1);
        }
    }

    // ---- epilogue: store h1 (bf16) + fused alpha dot products ----
    int gr0 = base + r0 + grp;
    int gr8 = gr0 + 8;
    float s_r0[4] = {0, 0, 0, 0}, s_r8[4] = {0, 0, 0, 0};
    float d_r0[4] = {0, 0, 0, 0}, d_r8[4] = {0, 0, 0, 0};
#pragma unroll
    for (int j = 0; j < 16; j++) {
        int c = 8 * j + 2 * tg;
        int h = j >> 2;
        float A0 = __ldg(&asrc[c]), A1 = __ldg(&asrc[c + 1]);
        float D0 = __ldg(&adst[c]), D1 = __ldg(&adst[c + 1]);
        s_r0[h] = fmaf(acc[j][0], A0, fmaf(acc[j][1], A1, s_r0[h]));
        s_r8[h] = fmaf(acc[j][2], A0, fmaf(acc[j][3], A1, s_r8[h]));
        d_r0[h] = fmaf(acc[j][0], D0, fmaf(acc[j][1], D1, d_r0[h]));
        d_r8[h] = fmaf(acc[j][2], D0, fmaf(acc[j][3], D1, d_r8[h]));
        if (gr0 < N)
            *(__nv_bfloat162*)&g_h1b[(size_t)gr0 * 128 + c] =
                __float22bfloat162_rn(make_float2(acc[j][0], acc[j][1]));
        if (gr8 < N)
            *(__nv_bfloat162*)&g_h1b[(size_t)gr8 * 128 + c] =
                __float22bfloat162_rn(make_float2(acc[j][2], acc[j][3]));
    }
#pragma unroll
    for (int h = 0; h < 4; h++) {
        s_r0[h] += __shfl_xor_sync(0xffffffffu, s_r0[h], 1);
        s_r0[h] += __shfl_xor_sync(0xffffffffu, s_r0[h], 2);
        s_r8[h] += __shfl_xor_sync(0xffffffffu, s_r8[h], 1);
        s_r8[h] += __shfl_xor_sync(0xffffffffu, s_r8[h], 2);
        d_r0[h] += __shfl_xor_sync(0xffffffffu, d_r0[h], 1);
        d_r0[h] += __shfl_xor_sync(0xffffffffu, d_r0[h], 2);
        d_r8[h] += __shfl_xor_sync(0xffffffffu, d_r8[h], 1);
        d_r8[h] += __shfl_xor_sync(0xffffffffu, d_r8[h], 2);
    }
    if (tg == 0) {
        if (gr0 < N) {
            g_as1[gr0] = make_float4(s_r0[0], s_r0[1], s_r0[2], s_r0[3]);
            g_ad1[gr0] = make_float4(d_r0[0], d_r0[1], d_r0[2], d_r0[3]);
        }
        if (gr8 < N) {
            g_as1[gr8] = make_float4(s_r8[0], s_r8[1], s_r8[2], s_r8[3]);
            g_ad1[gr8] = make_float4(d_r8[0], d_r8[1], d_r8[2], d_r8[3]);
        }
    }
}

// ---------------- layer1 softmax+aggregation fused with layer2 matvec ----------------
// Warp per dst node. acc (float4/lane) = full out1 row; then h2 = elu(acc+b1)@W2,
// as2/ad2 computed in-register. out1 never touches memory.
__global__ void agg1_layer2_kernel(const float* __restrict__ W2, const float* __restrict__ b1,
                                   const float* __restrict__ asrc2, const float* __restrict__ adst2,
                                   int N) {
    int gw = (blockIdx.x * blockDim.x + threadIdx.x) >> 5;
    int lane = threadIdx.x & 31;
    if (gw >= N) return;
    int row = g_rowstart[gw], end = g_rowstart[gw + 1];
    int deg = end - row;
    float4 d4 = g_ad1[gw];
    float4 acc = make_float4(0.f, 0.f, 0.f, 0.f);

    if (deg <= 32) {
        // fast path: one gather, weights live in registers
        int msrc = 0;
        float e0 = -1e30f, e1 = -1e30f, e2 = -1e30f, e3 = -1e30f;
        if (lane < deg) {
            msrc = __ldg(&g_srcs[row + lane]);
            float4 a = g_as1[msrc];
            e0 = lrelu(a.x + d4.x); e1 = lrelu(a.y + d4.y);
            e2 = lrelu(a.z + d4.z); e3 = lrelu(a.w + d4.w);
        }
        float M0 = wmaxf(e0), M1 = wmaxf(e1), M2 = wmaxf(e2), M3 = wmaxf(e3);
        float t0 = (lane < deg) ? __expf(e0 - M0) : 0.f;
        float t1 = (lane < deg) ? __expf(e1 - M1) : 0.f;
        float t2 = (lane < deg) ? __expf(e2 - M2) : 0.f;
        float t3 = (lane < deg) ? __expf(e3 - M3) : 0.f;
        float w0 = t0 / (wsumf(t0) + 1e-16f);
        float w1 = t1 / (wsumf(t1) + 1e-16f);
        float w2 = t2 / (wsumf(t2) + 1e-16f);
        float w3 = t3 / (wsumf(t3) + 1e-16f);
#pragma unroll 4
        for (int e = 0; e < deg; e++) {
            int   src = __shfl_sync(0xffffffffu, msrc, e);
            float b0  = __shfl_sync(0xffffffffu, w0, e);
            float b1v = __shfl_sync(0xffffffffu, w1, e);
            float b2v = __shfl_sync(0xffffffffu, w2, e);
            float b3  = __shfl_sync(0xffffffffu, w3, e);
            float wl = (lane & 8) ? b1v : b0;
            float wh = (lane & 8) ? b3 : b2v;
            float ws = (lane & 16) ? wh : wl;
            uint2 hv = *(const uint2*)(g_h1b + (size_t)src * 128 + lane * 4);
            float2 f0 = __bfloat1622float2(*(__nv_bfloat162*)&hv.x);
            float2 f1 = __bfloat1622float2(*(__nv_bfloat162*)&hv.y);
            acc.x = fmaf(ws, f0.x, acc.x);
            acc.y = fmaf(ws, f0.y, acc.y);
            acc.z = fmaf(ws, f1.x, acc.z);
            acc.w = fmaf(ws, f1.y, acc.w);
        }
    } else {
        // slow path (rare): 2-pass online softmax
        float m0 = -1e30f, m1 = -1e30f, m2 = -1e30f, m3 = -1e30f;
        float s0 = 0.f, s1 = 0.f, s2 = 0.f, s3 = 0.f;
        for (int j = row + lane; j < end; j += 32) {
            int src = __ldg(&g_srcs[j]);
            float4 a = g_as1[src];
            float e0 = lrelu(a.x + d4.x), e1 = lrelu(a.y + d4.y);
            float e2 = lrelu(a.z + d4.z), e3 = lrelu(a.w + d4.w);
            float n0 = fmaxf(m0, e0); s0 = s0 * __expf(m0 - n0) + __expf(e0 - n0); m0 = n0;
            float n1 = fmaxf(m1, e1); s1 = s1 * __expf(m1 - n1) + __expf(e1 - n1); m1 = n1;
            float n2 = fmaxf(m2, e2); s2 = s2 * __expf(m2 - n2) + __expf(e2 - n2); m2 = n2;
            float n3 = fmaxf(m3, e3); s3 = s3 * __expf(m3 - n3) + __expf(e3 - n3); m3 = n3;
        }
        float M0 = wmaxf(m0), M1 = wmaxf(m1), M2 = wmaxf(m2), M3 = wmaxf(m3);
        float i0 = 1.f / (wsumf(s0 * __expf(m0 - M0)) + 1e-16f);
        float i1 = 1.f / (wsumf(s1 * __expf(m1 - M1)) + 1e-16f);
        float i2 = 1.f / (wsumf(s2 * __expf(m2 - M2)) + 1e-16f);
        float i3 = 1.f / (wsumf(s3 * __expf(m3 - M3)) + 1e-16f);
        for (int cb = row; cb < end; cb += 32) {
            int rem = end - cb;
            int msrc = 0;
            float w0 = 0.f, w1 = 0.f, w2 = 0.f, w3 = 0.f;
            if (lane < rem) {
                msrc = __ldg(&g_srcs[cb + lane]);
                float4 a = g_as1[msrc];
                w0 = __expf(lrelu(a.x + d4.x) - M0) * i0;
                w1 = __expf(lrelu(a.y + d4.y) - M1) * i1;
                w2 = __expf(lrelu(a.z + d4.z) - M2) * i2;
                w3 = __expf(lrelu(a.w + d4.w) - M3) * i3;
            }
            int cnt = rem < 32 ? rem : 32;
            for (int e = 0; e < cnt; e++) {
                int   src = __shfl_sync(0xffffffffu, msrc, e);
                float b0  = __shfl_sync(0xffffffffu, w0, e);
                float b1v = __shfl_sync(0xffffffffu, w1, e);
                float b2v = __shfl_sync(0xffffffffu, w2, e);
                float b3  = __shfl_sync(0xffffffffu, w3, e);
                float wl = (lane & 8) ? b1v : b0;
                float wh = (lane & 8) ? b3 : b2v;
                float ws = (lane & 16) ? wh : wl;
                uint2 hv = *(const uint2*)(g_h1b + (size_t)src * 128 + lane * 4);
                float2 f0 = __bfloat1622float2(*(__nv_bfloat162*)&hv.x);
                float2 f1 = __bfloat1622float2(*(__nv_bfloat162*)&hv.y);
                acc.x = fmaf(ws, f0.x, acc.x);
                acc.y = fmaf(ws, f0.y, acc.y);
                acc.z = fmaf(ws, f1.x, acc.z);
                acc.w = fmaf(ws, f1.y, acc.w);
            }
        }
    }

    // ---- fused layer2: t = elu(acc + b1[lane*4..]); h2 = t @ W2 (128x8) ----
    float4 Bv = *(const float4*)&b1[lane * 4];
    float t0 = eluf(acc.x + Bv.x), t1 = eluf(acc.y + Bv.y);
    float t2 = eluf(acc.z + Bv.z), t3 = eluf(acc.w + Bv.w);
    // W2 rows lane*4 .. lane*4+3 (each row 8 floats)
    const float4* w2p = (const float4*)(W2 + lane * 32);
    float4 r0a = __ldg(&w2p[0]), r0b = __ldg(&w2p[1]);
    float4 r1a = __ldg(&w2p[2]), r1b = __ldg(&w2p[3]);
    float4 r2a = __ldg(&w2p[4]), r2b = __ldg(&w2p[5]);
    float4 r3a = __ldg(&w2p[6]), r3b = __ldg(&w2p[7]);
    float p[8];
    p[0] = t0 * r0a.x + t1 * r1a.x + t2 * r2a.x + t3 * r3a.x;
    p[1] = t0 * r0a.y + t1 * r1a.y + t2 * r2a.y + t3 * r3a.y;
    p[2] = t0 * r0a.z + t1 * r1a.z + t2 * r2a.z + t3 * r3a.z;
    p[3] = t0 * r0a.w + t1 * r1a.w + t2 * r2a.w + t3 * r3a.w;
    p[4] = t0 * r0b.x + t1 * r1b.x + t2 * r2b.x + t3 * r3b.x;
    p[5] = t0 * r0b.y + t1 * r1b.y + t2 * r2b.y + t3 * r3b.y;
    p[6] = t0 * r0b.z + t1 * r1b.z + t2 * r2b.z + t3 * r3b.z;
    p[7] = t0 * r0b.w + t1 * r1b.w + t2 * r2b.w + t3 * r3b.w;
#pragma unroll
    for (int c = 0; c < 8; c++) p[c] = wsumf(p[c]);
    if (lane == 0) {
        float s = 0.f, d = 0.f;
#pragma unroll
        for (int c = 0; c < 8; c++) {
            s = fmaf(p[c], __ldg(&asrc2[c]), s);
            d = fmaf(p[c], __ldg(&adst2[c]), d);
        }
        float4* hp = (float4*)(g_h2 + (size_t)gw * 8);
        hp[0] = make_float4(p[0], p[1], p[2], p[3]);
        hp[1] = make_float4(p[4], p[5], p[6], p[7]);
        g_as2[gw] = s;
        g_ad2[gw] = d;
    }
}

// ---------------- layer2 softmax + aggregation + final output (fused) ----------------
__global__ void agg2_final_kernel(const float* __restrict__ b2, const float* __restrict__ Wlin,
                                  const float* __restrict__ blin, float* __restrict__ out, int N) {
    int gw = (blockIdx.x * blockDim.x + threadIdx.x) >> 5;
    int lane = threadIdx.x & 31;
    if (gw >= N) return;
    int row = g_rowstart[gw], end = g_rowstart[gw + 1];
    int deg = end - row;
    float dd = g_ad2[gw];
    float a0 = 0.f, a1 = 0.f, a2 = 0.f, a3 = 0.f, a4 = 0.f, a5 = 0.f, a6 = 0.f, a7 = 0.f;

    if (deg <= 32) {
        int msrc = 0;
        float e = -1e30f;
        if (lane < deg) {
            msrc = __ldg(&g_srcs[row + lane]);
            e = lrelu(g_as2[msrc] + dd);
        }
        float M = wmaxf(e);
        float t = (lane < deg) ? __expf(e - M) : 0.f;
        float w = t / (wsumf(t) + 1e-16f);
        if (lane < deg) {
            const float4* hp = (const float4*)(g_h2 + (size_t)msrc * 8);
            float4 v0 = hp[0], v1 = hp[1];
            a0 = w * v0.x; a1 = w * v0.y; a2 = w * v0.z; a3 = w * v0.w;
            a4 = w * v1.x; a5 = w * v1.y; a6 = w * v1.z; a7 = w * v1.w;
        }
    } else {
        float m = -1e30f, s = 0.f;
        for (int j = row + lane; j < end; j += 32) {
            int src = __ldg(&g_srcs[j]);
            float e = lrelu(g_as2[src] + dd);
            float nm = fmaxf(m, e);
            s = s * __expf(m - nm) + __expf(e - nm);
            m = nm;
        }
        float M = wmaxf(m);
        float inv = 1.f / (wsumf(s * __expf(m - M)) + 1e-16f);
        for (int j = row + lane; j < end; j += 32) {
            int src = __ldg(&g_srcs[j]);
            float w = __expf(lrelu(g_as2[src] + dd) - M) * inv;
            const float4* hp = (const float4*)(g_h2 + (size_t)src * 8);
            float4 v0 = hp[0], v1 = hp[1];
            a0 = fmaf(w, v0.x, a0); a1 = fmaf(w, v0.y, a1);
            a2 = fmaf(w, v0.z, a2); a3 = fmaf(w, v0.w, a3);
            a4 = fmaf(w, v1.x, a4); a5 = fmaf(w, v1.y, a5);
            a6 = fmaf(w, v1.z, a6); a7 = fmaf(w, v1.w, a7);
        }
    }
    a0 = wsumf(a0); a1 = wsumf(a1); a2 = wsumf(a2); a3 = wsumf(a3);
    a4 = wsumf(a4); a5 = wsumf(a5); a6 = wsumf(a6); a7 = wsumf(a7);
    if (lane == 0) {
        float o[8] = {a0, a1, a2, a3, a4, a5, a6, a7};
        float y = __ldg(&blin[0]);
#pragma unroll
        for (int j = 0; j < 8; j++) {
            float t = eluf(o[j] + __ldg(&b2[j]));
            y = fmaf(t, __ldg(&Wlin[j]), y);
        }
        out[gw] = 1.f / (1.f + __expf(-y));
    }
}

// ---------------- launch ----------------
extern "C" void kernel_launch(void* const* d_in, const int* in_sizes, int n_in,
                              void* d_out, int out_size) {
    const float* x    = (const float*)d_in[0];
    const int*   ei   = (const int*)d_in[1];
    // d_in[2] edge_attr unused
    const float* W1   = (const float*)d_in[3];
    const float* as1  = (const float*)d_in[4];
    const float* ad1  = (const float*)d_in[5];
    const float* b1   = (const float*)d_in[6];
    const float* W2   = (const float*)d_in[7];
    const float* as2w = (const float*)d_in[8];
    const float* ad2w = (const float*)d_in[9];
    const float* b2   = (const float*)d_in[10];
    const float* Wlin = (const float*)d_in[11];
    const float* blin = (const float*)d_in[12];
    float* out = (float*)d_out;

    int N = in_sizes[0] / 128;
    int E = in_sizes[1] / 2;
    int Etot = E + N;
    int nch = (N + SCAN_CHUNK - 1) / SCAN_CHUNK;
    const int TB = 256;
    const int SMEM_GEMM = (256 * 132 + 128 * 136) * 4;  // 204800 B

    cudaFuncSetAttribute(gemm1_kernel, cudaFuncAttributeMaxDynamicSharedMemorySize, SMEM_GEMM);

    // Fork: CSR build (ei only) concurrent with gemm1 (x/W1 only).
    cudaStream_t s2;
    cudaStreamCreate(&s2);
    cudaEvent_t evFork, evJoin;
    cudaEventCreateWithFlags(&evFork, cudaEventDisableTiming);
    cudaEventCreateWithFlags(&evJoin, cudaEventDisableTiming);

    cudaEventRecord(evFork, 0);
    cudaStreamWaitEvent(s2, evFork, 0);

    zero_deg_kernel<<<(N + TB - 1) / TB, TB, 0, s2>>>(N);
    count_kernel<<<(Etot + TB - 1) / TB, TB, 0, s2>>>(ei, E, Etot);
    scan1_kernel<<<nch, SCAN_CHUNK, 0, s2>>>(N);
    scan2_kernel<<<1, SCAN_CHUNK, 0, s2>>>(nch);
    scan3_kernel<<<nch, SCAN_CHUNK, 0, s2>>>(N, Etot);
    fill_kernel<<<(Etot + TB - 1) / TB, TB, 0, s2>>>(ei, E, Etot);
    cudaEventRecord(evJoin, s2);

    gemm1_kernel<<<(N + 255) / 256, 512, SMEM_GEMM>>>(x, W1, as1, ad1, N);

    cudaStreamWaitEvent(0, evJoin, 0);
    agg1_layer2_kernel<<<(N * 32 + TB - 1) / TB, TB>>>(W2, b1, as2w, ad2w, N);
    agg2_final_kernel<<<(N * 32 + TB - 1) / TB, TB>>>(b2, Wlin, blin, out, N);

    cudaEventDestroy(evFork);
    cudaEventDestroy(evJoin);
    cudaStreamDestroy(s2);
}

// round 7
// speedup vs baseline: 1.2486x; 1.2486x over previous
#include <cuda_runtime.h>
#include <cuda_bf16.h>
#include <math.h>
#include <stdint.h>

#define NMAX 100000
#define EMAX 1600000
#define ETMAX (EMAX + NMAX)
#define SCAN_CHUNK 512

// ---------------- scratch (device globals; no allocation allowed) ----------------
__device__ __nv_bfloat16 g_h1b[NMAX * 128];   // layer1 features, bf16 (25.6 MB)
__device__ __nv_bfloat16 g_out1b[NMAX * 128]; // layer1 aggregated, bf16 (25.6 MB)
__device__ float4 g_as1[NMAX];                // alpha_src layer1 (4 heads)
__device__ float4 g_ad1[NMAX];                // alpha_dst layer1
__device__ float  g_h2[NMAX * 8];
__device__ float  g_as2[NMAX];
__device__ float  g_ad2[NMAX];
// CSR scratch
__device__ int    g_deg[NMAX];
__device__ int    g_rowstart[NMAX + 1];
__device__ int    g_fill[NMAX];
__device__ int    g_srcs[ETMAX];
__device__ int    g_csum[(NMAX + SCAN_CHUNK - 1) / SCAN_CHUNK];
__device__ int    g_coff[(NMAX + SCAN_CHUNK - 1) / SCAN_CHUNK];

// ---------------- helpers ----------------
__device__ __forceinline__ float lrelu(float v) { return v > 0.f ? v : 0.2f * v; }
__device__ __forceinline__ float eluf(float v)  { return v > 0.f ? v : (__expf(v) - 1.f); }
__device__ __forceinline__ float wmaxf(float v) {
#pragma unroll
    for (int o = 16; o; o >>= 1) v = fmaxf(v, __shfl_xor_sync(0xffffffffu, v, o));
    return v;
}
__device__ __forceinline__ float wsumf(float v) {
#pragma unroll
    for (int o = 16; o; o >>= 1) v += __shfl_xor_sync(0xffffffffu, v, o);
    return v;
}
__device__ __forceinline__ uint32_t f2tf32(float f) {
    uint32_t r; asm("cvt.rna.tf32.f32 %0, %1;" : "=r"(r) : "f"(f)); return r;
}
__device__ __forceinline__ void mma_tf32(float& d0, float& d1, float& d2, float& d3,
                                         uint32_t a0, uint32_t a1, uint32_t a2, uint32_t a3,
                                         uint32_t b0, uint32_t b1) {
    asm("mma.sync.aligned.m16n8k8.row.col.f32.tf32.tf32.f32 "
        "{%0,%1,%2,%3}, {%4,%5,%6,%7}, {%8,%9}, {%0,%1,%2,%3};"
        : "+f"(d0), "+f"(d1), "+f"(d2), "+f"(d3)
        : "r"(a0), "r"(a1), "r"(a2), "r"(a3), "r"(b0), "r"(b1));
}

// ---------------- CSR build ----------------
__global__ void zero_deg_kernel(int N) {
    int i = blockIdx.x * blockDim.x + threadIdx.x;
    if (i < N) g_deg[i] = 0;
}

__global__ void count_kernel(const int* __restrict__ ei, int E, int Etot) {
    int idx = blockIdx.x * blockDim.x + threadIdx.x;
    if (idx >= Etot) return;
    int dst = (idx < E) ? ei[E + idx] : (idx - E);
    atomicAdd(&g_deg[dst], 1);
}

__global__ void scan1_kernel(int N) {
    __shared__ int sh[SCAN_CHUNK];
    int t = threadIdx.x;
    int i = blockIdx.x * SCAN_CHUNK + t;
    sh[t] = (i < N) ? g_deg[i] : 0;
    __syncthreads();
#pragma unroll
    for (int s = SCAN_CHUNK / 2; s > 0; s >>= 1) {
        if (t < s) sh[t] += sh[t + s];
        __syncthreads();
    }
    if (t == 0) g_csum[blockIdx.x] = sh[0];
}

__global__ void scan2_kernel(int nch) {
    __shared__ int sh[SCAN_CHUNK];
    int t = threadIdx.x;
    int v = (t < nch) ? g_csum[t] : 0;
    sh[t] = v;
    __syncthreads();
#pragma unroll
    for (int off = 1; off < SCAN_CHUNK; off <<= 1) {
        int add = (t >= off) ? sh[t - off] : 0;
        __syncthreads();
        sh[t] += add;
        __syncthreads();
    }
    if (t < nch) g_coff[t] = sh[t] - v;
}

__global__ void scan3_kernel(int N, int Etot) {
    __shared__ int sh[SCAN_CHUNK];
    int t = threadIdx.x;
    int i = blockIdx.x * SCAN_CHUNK + t;
    int v = (i < N) ? g_deg[i] : 0;
    sh[t] = v;
    __syncthreads();
#pragma unroll
    for (int off = 1; off < SCAN_CHUNK; off <<= 1) {
        int add = (t >= off) ? sh[t - off] : 0;
        __syncthreads();
        sh[t] += add;
        __syncthreads();
    }
    if (i < N) {
        int excl = sh[t] - v + g_coff[blockIdx.x];
        g_rowstart[i] = excl;
        g_fill[i] = excl;
    }
    if (blockIdx.x == 0 && t == 0) g_rowstart[N] = Etot;
}

__global__ void fill_kernel(const int* __restrict__ ei, int E, int Etot) {
    int idx = blockIdx.x * blockDim.x + threadIdx.x;
    if (idx >= Etot) return;
    int src, dst;
    if (idx < E) { src = ei[idx]; dst = ei[E + idx]; } else { src = dst = idx - E; }
    int p = atomicAdd(&g_fill[dst], 1);
    g_srcs[p] = src;
}

// ---------------- layer1 GEMM (tf32 tensor cores) + fused alpha epilogue ----------------
__global__ __launch_bounds__(512) void gemm1_kernel(
    const float* __restrict__ x, const float* __restrict__ W,
    const float* __restrict__ asrc, const float* __restrict__ adst, int N) {
    extern __shared__ float sm[];
    float* xs = sm;               // 256*132
    float* wk = sm + 256 * 132;   // 128*136
    int tid = threadIdx.x;
    int base = blockIdx.x * 256;

    for (int i = tid; i < 4096; i += 512) {
        int k = i >> 5, c4 = i & 31;
        float4 v = ((const float4*)W)[i];
        float4 o;
        o.x = __uint_as_float(f2tf32(v.x));
        o.y = __uint_as_float(f2tf32(v.y));
        o.z = __uint_as_float(f2tf32(v.z));
        o.w = __uint_as_float(f2tf32(v.w));
        *(float4*)&wk[k * 136 + c4 * 4] = o;
    }
    for (int i = tid; i < 8192; i += 512) {
        int r = i >> 5, c4 = i & 31;
        int gr = base + r;
        float4 v = make_float4(0.f, 0.f, 0.f, 0.f);
        if (gr < N) v = ((const float4*)x)[gr * 32 + c4];
        float4 o;
        o.x = __uint_as_float(f2tf32(v.x));
        o.y = __uint_as_float(f2tf32(v.y));
        o.z = __uint_as_float(f2tf32(v.z));
        o.w = __uint_as_float(f2tf32(v.w));
        *(float4*)&xs[r * 132 + c4 * 4] = o;
    }
    __syncthreads();

    int w = tid >> 5, lane = tid & 31;
    int tg = lane & 3, grp = lane >> 2;
    int r0 = w * 16;

    float acc[16][4];
#pragma unroll
    for (int j = 0; j < 16; j++)
#pragma unroll
        for (int q = 0; q < 4; q++) acc[j][q] = 0.f;

#pragma unroll 4
    for (int ks = 0; ks < 16; ks++) {
        int k0 = ks * 8;
        const float* ax = xs + (r0 + grp) * 132 + k0 + tg;
        uint32_t a0 = __float_as_uint(ax[0]);
        uint32_t a1 = __float_as_uint(ax[8 * 132]);
        uint32_t a2 = __float_as_uint(ax[4]);
        uint32_t a3 = __float_as_uint(ax[8 * 132 + 4]);
        const float* bx = wk + (k0 + tg) * 136 + grp;
#pragma unroll
        for (int j = 0; j < 16; j++) {
            uint32_t b0 = __float_as_uint(bx[8 * j]);
            uint32_t b1 = __float_as_uint(bx[4 * 136 + 8 * j]);
            mma_tf32(acc[j][0], acc[j][1], acc[j][2], acc[j][3], a0, a1, a2, a3, b0, b1);
        }
    }

    // ---- epilogue: store h1 (bf16) + fused alpha dot products ----
    int gr0 = base + r0 + grp;
    int gr8 = gr0 + 8;
    float s_r0[4] = {0, 0, 0, 0}, s_r8[4] = {0, 0, 0, 0};
    float d_r0[4] = {0, 0, 0, 0}, d_r8[4] = {0, 0, 0, 0};
#pragma unroll
    for (int j = 0; j < 16; j++) {
        int c = 8 * j + 2 * tg;
        int h = j >> 2;
        float A0 = __ldg(&asrc[c]), A1 = __ldg(&asrc[c + 1]);
        float D0 = __ldg(&adst[c]), D1 = __ldg(&adst[c + 1]);
        s_r0[h] = fmaf(acc[j][0], A0, fmaf(acc[j][1], A1, s_r0[h]));
        s_r8[h] = fmaf(acc[j][2], A0, fmaf(acc[j][3], A1, s_r8[h]));
        d_r0[h] = fmaf(acc[j][0], D0, fmaf(acc[j][1], D1, d_r0[h]));
        d_r8[h] = fmaf(acc[j][2], D0, fmaf(acc[j][3], D1, d_r8[h]));
        if (gr0 < N)
            *(__nv_bfloat162*)&g_h1b[(size_t)gr0 * 128 + c] =
                __float22bfloat162_rn(make_float2(acc[j][0], acc[j][1]));
        if (gr8 < N)
            *(__nv_bfloat162*)&g_h1b[(size_t)gr8 * 128 + c] =
                __float22bfloat162_rn(make_float2(acc[j][2], acc[j][3]));
    }
#pragma unroll
    for (int h = 0; h < 4; h++) {
        s_r0[h] += __shfl_xor_sync(0xffffffffu, s_r0[h], 1);
        s_r0[h] += __shfl_xor_sync(0xffffffffu, s_r0[h], 2);
        s_r8[h] += __shfl_xor_sync(0xffffffffu, s_r8[h], 1);
        s_r8[h] += __shfl_xor_sync(0xffffffffu, s_r8[h], 2);
        d_r0[h] += __shfl_xor_sync(0xffffffffu, d_r0[h], 1);
        d_r0[h] += __shfl_xor_sync(0xffffffffu, d_r0[h], 2);
        d_r8[h] += __shfl_xor_sync(0xffffffffu, d_r8[h], 1);
        d_r8[h] += __shfl_xor_sync(0xffffffffu, d_r8[h], 2);
    }
    if (tg == 0) {
        if (gr0 < N) {
            g_as1[gr0] = make_float4(s_r0[0], s_r0[1], s_r0[2], s_r0[3]);
            g_ad1[gr0] = make_float4(d_r0[0], d_r0[1], d_r0[2], d_r0[3]);
        }
        if (gr8 < N) {
            g_as1[gr8] = make_float4(s_r8[0], s_r8[1], s_r8[2], s_r8[3]);
            g_ad1[gr8] = make_float4(d_r8[0], d_r8[1], d_r8[2], d_r8[3]);
        }
    }
}

// ---------------- layer1 fused softmax + aggregation: warp per dst ----------------
__global__ void agg1_kernel(int N) {
    int gw = (blockIdx.x * blockDim.x + threadIdx.x) >> 5;
    int lane = threadIdx.x & 31;
    if (gw >= N) return;
    int row = g_rowstart[gw], end = g_rowstart[gw + 1];
    int deg = end - row;
    float4 d4 = g_ad1[gw];
    float4 acc = make_float4(0.f, 0.f, 0.f, 0.f);

    if (deg <= 32) {
        int msrc = 0;
        float e0 = -1e30f, e1 = -1e30f, e2 = -1e30f, e3 = -1e30f;
        if (lane < deg) {
            msrc = __ldg(&g_srcs[row + lane]);
            float4 a = g_as1[msrc];
            e0 = lrelu(a.x + d4.x); e1 = lrelu(a.y + d4.y);
            e2 = lrelu(a.z + d4.z); e3 = lrelu(a.w + d4.w);
        }
        float M0 = wmaxf(e0), M1 = wmaxf(e1), M2 = wmaxf(e2), M3 = wmaxf(e3);
        float t0 = (lane < deg) ? __expf(e0 - M0) : 0.f;
        float t1 = (lane < deg) ? __expf(e1 - M1) : 0.f;
        float t2 = (lane < deg) ? __expf(e2 - M2) : 0.f;
        float t3 = (lane < deg) ? __expf(e3 - M3) : 0.f;
        float w0 = t0 / (wsumf(t0) + 1e-16f);
        float w1 = t1 / (wsumf(t1) + 1e-16f);
        float w2 = t2 / (wsumf(t2) + 1e-16f);
        float w3 = t3 / (wsumf(t3) + 1e-16f);
#pragma unroll 4
        for (int e = 0; e < deg; e++) {
            int   src = __shfl_sync(0xffffffffu, msrc, e);
            float b0  = __shfl_sync(0xffffffffu, w0, e);
            float b1v = __shfl_sync(0xffffffffu, w1, e);
            float b2v = __shfl_sync(0xffffffffu, w2, e);
            float b3  = __shfl_sync(0xffffffffu, w3, e);
            float wl = (lane & 8) ? b1v : b0;
            float wh = (lane & 8) ? b3 : b2v;
            float ws = (lane & 16) ? wh : wl;
            uint2 hv = *(const uint2*)(g_h1b + (size_t)src * 128 + lane * 4);
            float2 f0 = __bfloat1622float2(*(__nv_bfloat162*)&hv.x);
            float2 f1 = __bfloat1622float2(*(__nv_bfloat162*)&hv.y);
            acc.x = fmaf(ws, f0.x, acc.x);
            acc.y = fmaf(ws, f0.y, acc.y);
            acc.z = fmaf(ws, f1.x, acc.z);
            acc.w = fmaf(ws, f1.y, acc.w);
        }
    } else {
        float m0 = -1e30f, m1 = -1e30f, m2 = -1e30f, m3 = -1e30f;
        float s0 = 0.f, s1 = 0.f, s2 = 0.f, s3 = 0.f;
        for (int j = row + lane; j < end; j += 32) {
            int src = __ldg(&g_srcs[j]);
            float4 a = g_as1[src];
            float e0 = lrelu(a.x + d4.x), e1 = lrelu(a.y + d4.y);
            float e2 = lrelu(a.z + d4.z), e3 = lrelu(a.w + d4.w);
            float n0 = fmaxf(m0, e0); s0 = s0 * __expf(m0 - n0) + __expf(e0 - n0); m0 = n0;
            float n1 = fmaxf(m1, e1); s1 = s1 * __expf(m1 - n1) + __expf(e1 - n1); m1 = n1;
            float n2 = fmaxf(m2, e2); s2 = s2 * __expf(m2 - n2) + __expf(e2 - n2); m2 = n2;
            float n3 = fmaxf(m3, e3); s3 = s3 * __expf(m3 - n3) + __expf(e3 - n3); m3 = n3;
        }
        float M0 = wmaxf(m0), M1 = wmaxf(m1), M2 = wmaxf(m2), M3 = wmaxf(m3);
        float i0 = 1.f / (wsumf(s0 * __expf(m0 - M0)) + 1e-16f);
        float i1 = 1.f / (wsumf(s1 * __expf(m1 - M1)) + 1e-16f);
        float i2 = 1.f / (wsumf(s2 * __expf(m2 - M2)) + 1e-16f);
        float i3 = 1.f / (wsumf(s3 * __expf(m3 - M3)) + 1e-16f);
        for (int cb = row; cb < end; cb += 32) {
            int rem = end - cb;
            int msrc = 0;
            float w0 = 0.f, w1 = 0.f, w2 = 0.f, w3 = 0.f;
            if (lane < rem) {
                msrc = __ldg(&g_srcs[cb + lane]);
                float4 a = g_as1[msrc];
                w0 = __expf(lrelu(a.x + d4.x) - M0) * i0;
                w1 = __expf(lrelu(a.y + d4.y) - M1) * i1;
                w2 = __expf(lrelu(a.z + d4.z) - M2) * i2;
                w3 = __expf(lrelu(a.w + d4.w) - M3) * i3;
            }
            int cnt = rem < 32 ? rem : 32;
            for (int e = 0; e < cnt; e++) {
                int   src = __shfl_sync(0xffffffffu, msrc, e);
                float b0  = __shfl_sync(0xffffffffu, w0, e);
                float b1v = __shfl_sync(0xffffffffu, w1, e);
                float b2v = __shfl_sync(0xffffffffu, w2, e);
                float b3  = __shfl_sync(0xffffffffu, w3, e);
                float wl = (lane & 8) ? b1v : b0;
                float wh = (lane & 8) ? b3 : b2v;
                float ws = (lane & 16) ? wh : wl;
                uint2 hv = *(const uint2*)(g_h1b + (size_t)src * 128 + lane * 4);
                float2 f0 = __bfloat1622float2(*(__nv_bfloat162*)&hv.x);
                float2 f1 = __bfloat1622float2(*(__nv_bfloat162*)&hv.y);
                acc.x = fmaf(ws, f0.x, acc.x);
                acc.y = fmaf(ws, f0.y, acc.y);
                acc.z = fmaf(ws, f1.x, acc.z);
                acc.w = fmaf(ws, f1.y, acc.w);
            }
        }
    }
    // store out1 as bf16 (8 bytes/lane, coalesced)
    __nv_bfloat162 o0 = __float22bfloat162_rn(make_float2(acc.x, acc.y));
    __nv_bfloat162 o1 = __float22bfloat162_rn(make_float2(acc.z, acc.w));
    uint2 ov;
    ov.x = *(uint32_t*)&o0;
    ov.y = *(uint32_t*)&o1;
    *(uint2*)(g_out1b + (size_t)gw * 128 + lane * 4) = ov;
}

// ---------------- layer2: h2 = elu(out1+b1) @ W2, plus attention scores ----------------
__global__ void layer2_kernel(const float* __restrict__ W2, const float* __restrict__ b1,
                              const float* __restrict__ asrc2, const float* __restrict__ adst2, int N) {
    __shared__ float w2s[128 * 8];
    __shared__ float b1s[128];
    __shared__ float s2s[8], d2s[8];
    int tid = threadIdx.x;
    for (int i = tid; i < 1024; i += 256) w2s[i] = W2[i];
    if (tid < 128) b1s[tid] = b1[tid];
    if (tid < 8) { s2s[tid] = asrc2[tid]; d2s[tid] = adst2[tid]; }
    __syncthreads();
    int n = blockIdx.x * 256 + tid;
    if (n >= N) return;
    float acc[8];
#pragma unroll
    for (int c = 0; c < 8; c++) acc[c] = 0.f;
    const uint4* op = (const uint4*)&g_out1b[(size_t)n * 128];  // 8 bf16 per uint4
#pragma unroll 4
    for (int k8 = 0; k8 < 16; k8++) {
        uint4 v = op[k8];
        float2 f0 = __bfloat1622float2(*(__nv_bfloat162*)&v.x);
        float2 f1 = __bfloat1622float2(*(__nv_bfloat162*)&v.y);
        float2 f2 = __bfloat1622float2(*(__nv_bfloat162*)&v.z);
        float2 f3 = __bfloat1622float2(*(__nv_bfloat162*)&v.w);
        float vv[8] = {f0.x, f0.y, f1.x, f1.y, f2.x, f2.y, f3.x, f3.y};
#pragma unroll
        for (int j = 0; j < 8; j++) {
            int k = k8 * 8 + j;
            float tv = eluf(vv[j] + b1s[k]);
#pragma unroll
            for (int c = 0; c < 8; c++) acc[c] = fmaf(tv, w2s[k * 8 + c], acc[c]);
        }
    }
    ((float4*)&g_h2[n * 8])[0] = make_float4(acc[0], acc[1], acc[2], acc[3]);
    ((float4*)&g_h2[n * 8])[1] = make_float4(acc[4], acc[5], acc[6], acc[7]);
    float s = 0.f, d = 0.f;
#pragma unroll
    for (int c = 0; c < 8; c++) { s += acc[c] * s2s[c]; d += acc[c] * d2s[c]; }
    g_as2[n] = s;
    g_ad2[n] = d;
}

// ---------------- layer2 softmax + aggregation + final output (fused) ----------------
__global__ void agg2_final_kernel(const float* __restrict__ b2, const float* __restrict__ Wlin,
                                  const float* __restrict__ blin, float* __restrict__ out, int N) {
    int gw = (blockIdx.x * blockDim.x + threadIdx.x) >> 5;
    int lane = threadIdx.x & 31;
    if (gw >= N) return;
    int row = g_rowstart[gw], end = g_rowstart[gw + 1];
    int deg = end - row;
    float dd = g_ad2[gw];
    float a0 = 0.f, a1 = 0.f, a2 = 0.f, a3 = 0.f, a4 = 0.f, a5 = 0.f, a6 = 0.f, a7 = 0.f;

    if (deg <= 32) {
        int msrc = 0;
        float e = -1e30f;
        if (lane < deg) {
            msrc = __ldg(&g_srcs[row + lane]);
            e = lrelu(g_as2[msrc] + dd);
        }
        float M = wmaxf(e);
        float t = (lane < deg) ? __expf(e - M) : 0.f;
        float w = t / (wsumf(t) + 1e-16f);
        if (lane < deg) {
            const float4* hp = (const float4*)(g_h2 + (size_t)msrc * 8);
            float4 v0 = hp[0], v1 = hp[1];
            a0 = w * v0.x; a1 = w * v0.y; a2 = w * v0.z; a3 = w * v0.w;
            a4 = w * v1.x; a5 = w * v1.y; a6 = w * v1.z; a7 = w * v1.w;
        }
    } else {
        float m = -1e30f, s = 0.f;
        for (int j = row + lane; j < end; j += 32) {
            int src = __ldg(&g_srcs[j]);
            float e = lrelu(g_as2[src] + dd);
            float nm = fmaxf(m, e);
            s = s * __expf(m - nm) + __expf(e - nm);
            m = nm;
        }
        float M = wmaxf(m);
        float inv = 1.f / (wsumf(s * __expf(m - M)) + 1e-16f);
        for (int j = row + lane; j < end; j += 32) {
            int src = __ldg(&g_srcs[j]);
            float w = __expf(lrelu(g_as2[src] + dd) - M) * inv;
            const float4* hp = (const float4*)(g_h2 + (size_t)src * 8);
            float4 v0 = hp[0], v1 = hp[1];
            a0 = fmaf(w, v0.x, a0); a1 = fmaf(w, v0.y, a1);
            a2 = fmaf(w, v0.z, a2); a3 = fmaf(w, v0.w, a3);
            a4 = fmaf(w, v1.x, a4); a5 = fmaf(w, v1.y, a5);
            a6 = fmaf(w, v1.z, a6); a7 = fmaf(w, v1.w, a7);
        }
    }
    a0 = wsumf(a0); a1 = wsumf(a1); a2 = wsumf(a2); a3 = wsumf(a3);
    a4 = wsumf(a4); a5 = wsumf(a5); a6 = wsumf(a6); a7 = wsumf(a7);
    if (lane == 0) {
        float o[8] = {a0, a1, a2, a3, a4, a5, a6, a7};
        float y = __ldg(&blin[0]);
#pragma unroll
        for (int j = 0; j < 8; j++) {
            float t = eluf(o[j] + __ldg(&b2[j]));
            y = fmaf(t, __ldg(&Wlin[j]), y);
        }
        out[gw] = 1.f / (1.f + __expf(-y));
    }
}

// ---------------- launch ----------------
extern "C" void kernel_launch(void* const* d_in, const int* in_sizes, int n_in,
                              void* d_out, int out_size) {
    const float* x    = (const float*)d_in[0];
    const int*   ei   = (const int*)d_in[1];
    // d_in[2] edge_attr unused
    const float* W1   = (const float*)d_in[3];
    const float* as1  = (const float*)d_in[4];
    const float* ad1  = (const float*)d_in[5];
    const float* b1   = (const float*)d_in[6];
    const float* W2   = (const float*)d_in[7];
    const float* as2w = (const float*)d_in[8];
    const float* ad2w = (const float*)d_in[9];
    const float* b2   = (const float*)d_in[10];
    const float* Wlin = (const float*)d_in[11];
    const float* blin = (const float*)d_in[12];
    float* out = (float*)d_out;

    int N = in_sizes[0] / 128;
    int E = in_sizes[1] / 2;
    int Etot = E + N;
    int nch = (N + SCAN_CHUNK - 1) / SCAN_CHUNK;
    const int TB = 256;
    const int SMEM_GEMM = (256 * 132 + 128 * 136) * 4;  // 204800 B

    cudaFuncSetAttribute(gemm1_kernel, cudaFuncAttributeMaxDynamicSharedMemorySize, SMEM_GEMM);

    // Fork: CSR build (ei only) concurrent with gemm1 (x/W1 only).
    cudaStream_t s2;
    cudaStreamCreate(&s2);
    cudaEvent_t evFork, evJoin;
    cudaEventCreateWithFlags(&evFork, cudaEventDisableTiming);
    cudaEventCreateWithFlags(&evJoin, cudaEventDisableTiming);

    cudaEventRecord(evFork, 0);
    cudaStreamWaitEvent(s2, evFork, 0);

    zero_deg_kernel<<<(N + TB - 1) / TB, TB, 0, s2>>>(N);
    count_kernel<<<(Etot + TB - 1) / TB, TB, 0, s2>>>(ei, E, Etot);
    scan1_kernel<<<nch, SCAN_CHUNK, 0, s2>>>(N);
    scan2_kernel<<<1, SCAN_CHUNK, 0, s2>>>(nch);
    scan3_kernel<<<nch, SCAN_CHUNK, 0, s2>>>(N, Etot);
    fill_kernel<<<(Etot + TB - 1) / TB, TB, 0, s2>>>(ei, E, Etot);
    cudaEventRecord(evJoin, s2);

    gemm1_kernel<<<(N + 255) / 256, 512, SMEM_GEMM>>>(x, W1, as1, ad1, N);

    cudaStreamWaitEvent(0, evJoin, 0);
    agg1_kernel<<<(N * 32 + TB - 1) / TB, TB>>>(N);
    layer2_kernel<<<(N + TB - 1) / TB, TB>>>(W2, b1, as2w, ad2w, N);
    agg2_final_kernel<<<(N * 32 + TB - 1) / TB, TB>>>(b2, Wlin, blin, out, N);

    cudaEventDestroy(evFork);
    cudaEventDestroy(evJoin);
    cudaStreamDestroy(s2);
}

// round 8
// speedup vs baseline: 1.2868x; 1.0306x over previous
#include <cuda_runtime.h>
#include <cuda_bf16.h>
#include <math.h>
#include <stdint.h>

#define NMAX 100000
#define EMAX 1600000
#define ETMAX (EMAX + NMAX)
#define SCAN_CHUNK 512

// ---------------- scratch (device globals; no allocation allowed) ----------------
__device__ __nv_bfloat16 g_h1b[NMAX * 128];   // layer1 features, bf16 (25.6 MB)
__device__ __nv_bfloat16 g_out1b[NMAX * 128]; // layer1 aggregated, bf16 (25.6 MB)
__device__ float4 g_as1[NMAX];                // alpha_src layer1 (4 heads)
__device__ float4 g_ad1[NMAX];                // alpha_dst layer1
__device__ float  g_h2[NMAX * 8];
__device__ float  g_as2[NMAX];
__device__ float  g_ad2[NMAX];
// CSR scratch
__device__ int    g_deg[NMAX];
__device__ int    g_rowstart[NMAX + 1];
__device__ int    g_eslot[ETMAX];             // per-edge slot within its dst row (6.8 MB)
__device__ int    g_srcs[ETMAX];
__device__ int    g_csum[(NMAX + SCAN_CHUNK - 1) / SCAN_CHUNK];
__device__ int    g_coff[(NMAX + SCAN_CHUNK - 1) / SCAN_CHUNK];

// ---------------- helpers ----------------
__device__ __forceinline__ float lrelu(float v) { return v > 0.f ? v : 0.2f * v; }
__device__ __forceinline__ float eluf(float v)  { return v > 0.f ? v : (__expf(v) - 1.f); }
__device__ __forceinline__ float wmaxf(float v) {
#pragma unroll
    for (int o = 16; o; o >>= 1) v = fmaxf(v, __shfl_xor_sync(0xffffffffu, v, o));
    return v;
}
__device__ __forceinline__ float wsumf(float v) {
#pragma unroll
    for (int o = 16; o; o >>= 1) v += __shfl_xor_sync(0xffffffffu, v, o);
    return v;
}
__device__ __forceinline__ uint32_t f2tf32(float f) {
    uint32_t r; asm("cvt.rna.tf32.f32 %0, %1;" : "=r"(r) : "f"(f)); return r;
}
__device__ __forceinline__ void mma_tf32(float& d0, float& d1, float& d2, float& d3,
                                         uint32_t a0, uint32_t a1, uint32_t a2, uint32_t a3,
                                         uint32_t b0, uint32_t b1) {
    asm("mma.sync.aligned.m16n8k8.row.col.f32.tf32.tf32.f32 "
        "{%0,%1,%2,%3}, {%4,%5,%6,%7}, {%8,%9}, {%0,%1,%2,%3};"
        : "+f"(d0), "+f"(d1), "+f"(d2), "+f"(d3)
        : "r"(a0), "r"(a1), "r"(a2), "r"(a3), "r"(b0), "r"(b1));
}

// ---------------- CSR build ----------------
__global__ void zero_deg_kernel(int N) {
    int i = blockIdx.x * blockDim.x + threadIdx.x;
    if (i < N) g_deg[i] = 0;
}

__global__ void count_kernel(const int* __restrict__ ei, int E, int Etot) {
    int idx = blockIdx.x * blockDim.x + threadIdx.x;
    if (idx >= Etot) return;
    int dst = (idx < E) ? ei[E + idx] : (idx - E);
    int slot = atomicAdd(&g_deg[dst], 1);
    g_eslot[idx] = slot;   // coalesced; reused by fill to avoid a second scattered atomic
}

__global__ void scan1_kernel(int N) {
    __shared__ int sh[SCAN_CHUNK];
    int t = threadIdx.x;
    int i = blockIdx.x * SCAN_CHUNK + t;
    sh[t] = (i < N) ? g_deg[i] : 0;
    __syncthreads();
#pragma unroll
    for (int s = SCAN_CHUNK / 2; s > 0; s >>= 1) {
        if (t < s) sh[t] += sh[t + s];
        __syncthreads();
    }
    if (t == 0) g_csum[blockIdx.x] = sh[0];
}

__global__ void scan2_kernel(int nch) {
    __shared__ int sh[SCAN_CHUNK];
    int t = threadIdx.x;
    int v = (t < nch) ? g_csum[t] : 0;
    sh[t] = v;
    __syncthreads();
#pragma unroll
    for (int off = 1; off < SCAN_CHUNK; off <<= 1) {
        int add = (t >= off) ? sh[t - off] : 0;
        __syncthreads();
        sh[t] += add;
        __syncthreads();
    }
    if (t < nch) g_coff[t] = sh[t] - v;
}

__global__ void scan3_kernel(int N, int Etot) {
    __shared__ int sh[SCAN_CHUNK];
    int t = threadIdx.x;
    int i = blockIdx.x * SCAN_CHUNK + t;
    int v = (i < N) ? g_deg[i] : 0;
    sh[t] = v;
    __syncthreads();
#pragma unroll
    for (int off = 1; off < SCAN_CHUNK; off <<= 1) {
        int add = (t >= off) ? sh[t - off] : 0;
        __syncthreads();
        sh[t] += add;
        __syncthreads();
    }
    if (i < N) g_rowstart[i] = sh[t] - v + g_coff[blockIdx.x];
    if (blockIdx.x == 0 && t == 0) g_rowstart[N] = Etot;
}

__global__ void fill_kernel(const int* __restrict__ ei, int E, int Etot) {
    int idx = blockIdx.x * blockDim.x + threadIdx.x;
    if (idx >= Etot) return;
    int src, dst;
    if (idx < E) { src = ei[idx]; dst = ei[E + idx]; } else { src = dst = idx - E; }
    g_srcs[g_rowstart[dst] + g_eslot[idx]] = src;  // no atomic: slot precomputed in count
}

// ---------------- layer1 GEMM (tf32 tensor cores) + fused alpha epilogue ----------------
__global__ __launch_bounds__(512) void gemm1_kernel(
    const float* __restrict__ x, const float* __restrict__ W,
    const float* __restrict__ asrc, const float* __restrict__ adst, int N) {
    extern __shared__ float sm[];
    float* xs = sm;               // 256*132
    float* wk = sm + 256 * 132;   // 128*136
    int tid = threadIdx.x;
    int base = blockIdx.x * 256;

    for (int i = tid; i < 4096; i += 512) {
        int k = i >> 5, c4 = i & 31;
        float4 v = ((const float4*)W)[i];
        float4 o;
        o.x = __uint_as_float(f2tf32(v.x));
        o.y = __uint_as_float(f2tf32(v.y));
        o.z = __uint_as_float(f2tf32(v.z));
        o.w = __uint_as_float(f2tf32(v.w));
        *(float4*)&wk[k * 136 + c4 * 4] = o;
    }
    for (int i = tid; i < 8192; i += 512) {
        int r = i >> 5, c4 = i & 31;
        int gr = base + r;
        float4 v = make_float4(0.f, 0.f, 0.f, 0.f);
        if (gr < N) v = ((const float4*)x)[gr * 32 + c4];
        float4 o;
        o.x = __uint_as_float(f2tf32(v.x));
        o.y = __uint_as_float(f2tf32(v.y));
        o.z = __uint_as_float(f2tf32(v.z));
        o.w = __uint_as_float(f2tf32(v.w));
        *(float4*)&xs[r * 132 + c4 * 4] = o;
    }
    __syncthreads();

    int w = tid >> 5, lane = tid & 31;
    int tg = lane & 3, grp = lane >> 2;
    int r0 = w * 16;

    float acc[16][4];
#pragma unroll
    for (int j = 0; j < 16; j++)
#pragma unroll
        for (int q = 0; q < 4; q++) acc[j][q] = 0.f;

#pragma unroll 4
    for (int ks = 0; ks < 16; ks++) {
        int k0 = ks * 8;
        const float* ax = xs + (r0 + grp) * 132 + k0 + tg;
        uint32_t a0 = __float_as_uint(ax[0]);
        uint32_t a1 = __float_as_uint(ax[8 * 132]);
        uint32_t a2 = __float_as_uint(ax[4]);
        uint32_t a3 = __float_as_uint(ax[8 * 132 + 4]);
        const float* bx = wk + (k0 + tg) * 136 + grp;
#pragma unroll
        for (int j = 0; j < 16; j++) {
            uint32_t b0 = __float_as_uint(bx[8 * j]);
            uint32_t b1 = __float_as_uint(bx[4 * 136 + 8 * j]);
            mma_tf32(acc[j][0], acc[j][1], acc[j][2], acc[j][3], a0, a1, a2, a3, b0, b1);
        }
    }

    // ---- epilogue: store h1 (bf16) + fused alpha dot products ----
    int gr0 = base + r0 + grp;
    int gr8 = gr0 + 8;
    float s_r0[4] = {0, 0, 0, 0}, s_r8[4] = {0, 0, 0, 0};
    float d_r0[4] = {0, 0, 0, 0}, d_r8[4] = {0, 0, 0, 0};
#pragma unroll
    for (int j = 0; j < 16; j++) {
        int c = 8 * j + 2 * tg;
        int h = j >> 2;
        float A0 = __ldg(&asrc[c]), A1 = __ldg(&asrc[c + 1]);
        float D0 = __ldg(&adst[c]), D1 = __ldg(&adst[c + 1]);
        s_r0[h] = fmaf(acc[j][0], A0, fmaf(acc[j][1], A1, s_r0[h]));
        s_r8[h] = fmaf(acc[j][2], A0, fmaf(acc[j][3], A1, s_r8[h]));
        d_r0[h] = fmaf(acc[j][0], D0, fmaf(acc[j][1], D1, d_r0[h]));
        d_r8[h] = fmaf(acc[j][2], D0, fmaf(acc[j][3], D1, d_r8[h]));
        if (gr0 < N)
            *(__nv_bfloat162*)&g_h1b[(size_t)gr0 * 128 + c] =
                __float22bfloat162_rn(make_float2(acc[j][0], acc[j][1]));
        if (gr8 < N)
            *(__nv_bfloat162*)&g_h1b[(size_t)gr8 * 128 + c] =
                __float22bfloat162_rn(make_float2(acc[j][2], acc[j][3]));
    }
#pragma unroll
    for (int h = 0; h < 4; h++) {
        s_r0[h] += __shfl_xor_sync(0xffffffffu, s_r0[h], 1);
        s_r0[h] += __shfl_xor_sync(0xffffffffu, s_r0[h], 2);
        s_r8[h] += __shfl_xor_sync(0xffffffffu, s_r8[h], 1);
        s_r8[h] += __shfl_xor_sync(0xffffffffu, s_r8[h], 2);
        d_r0[h] += __shfl_xor_sync(0xffffffffu, d_r0[h], 1);
        d_r0[h] += __shfl_xor_sync(0xffffffffu, d_r0[h], 2);
        d_r8[h] += __shfl_xor_sync(0xffffffffu, d_r8[h], 1);
        d_r8[h] += __shfl_xor_sync(0xffffffffu, d_r8[h], 2);
    }
    if (tg == 0) {
        if (gr0 < N) {
            g_as1[gr0] = make_float4(s_r0[0], s_r0[1], s_r0[2], s_r0[3]);
            g_ad1[gr0] = make_float4(d_r0[0], d_r0[1], d_r0[2], d_r0[3]);
        }
        if (gr8 < N) {
            g_as1[gr8] = make_float4(s_r8[0], s_r8[1], s_r8[2], s_r8[3]);
            g_ad1[gr8] = make_float4(d_r8[0], d_r8[1], d_r8[2], d_r8[3]);
        }
    }
}

// ---------------- layer1 fused softmax + aggregation: warp per dst ----------------
__global__ void agg1_kernel(int N) {
    int gw = (blockIdx.x * blockDim.x + threadIdx.x) >> 5;
    int lane = threadIdx.x & 31;
    if (gw >= N) return;
    int row = g_rowstart[gw], end = g_rowstart[gw + 1];
    int deg = end - row;
    float4 d4 = g_ad1[gw];

    if (deg <= 32) {
        // ---- fast path: weights in registers, 2 edges per iteration ----
        int msrc = 0;
        float e0 = -1e30f, e1 = -1e30f, e2 = -1e30f, e3 = -1e30f;
        if (lane < deg) {
            msrc = __ldg(&g_srcs[row + lane]);
            float4 a = g_as1[msrc];
            e0 = lrelu(a.x + d4.x); e1 = lrelu(a.y + d4.y);
            e2 = lrelu(a.z + d4.z); e3 = lrelu(a.w + d4.w);
        }
        float M0 = wmaxf(e0), M1 = wmaxf(e1), M2 = wmaxf(e2), M3 = wmaxf(e3);
        float t0 = (lane < deg) ? __expf(e0 - M0) : 0.f;
        float t1 = (lane < deg) ? __expf(e1 - M1) : 0.f;
        float t2 = (lane < deg) ? __expf(e2 - M2) : 0.f;
        float t3 = (lane < deg) ? __expf(e3 - M3) : 0.f;
        float w0 = t0 / (wsumf(t0) + 1e-16f);
        float w1 = t1 / (wsumf(t1) + 1e-16f);
        float w2 = t2 / (wsumf(t2) + 1e-16f);
        float w3 = t3 / (wsumf(t3) + 1e-16f);

        // lanes 0-15 -> edge e, lanes 16-31 -> edge e+1; each lane covers 8 columns (16B)
        int half = lane >> 4;     // 0 or 1
        int hl = lane & 15;       // column group 0..15 (cols hl*8 .. hl*8+7)
        int head = hl >> 2;       // cols hl*8 span one head: head = hl/4
        float a8[8];
#pragma unroll
        for (int j = 0; j < 8; j++) a8[j] = 0.f;

#pragma unroll 4
        for (int e = 0; e < deg; e += 2) {
            int idx = e + half;   // <= 31 always (deg odd => deg <= 31); idx==deg lanes have w=0
            int   src = __shfl_sync(0xffffffffu, msrc, idx);
            float b0  = __shfl_sync(0xffffffffu, w0, idx);
            float b1v = __shfl_sync(0xffffffffu, w1, idx);
            float b2v = __shfl_sync(0xffffffffu, w2, idx);
            float b3  = __shfl_sync(0xffffffffu, w3, idx);
            float wl = (head & 1) ? b1v : b0;
            float wh = (head & 1) ? b3 : b2v;
            float ws = (head & 2) ? wh : wl;
            uint4 hv = *(const uint4*)(g_h1b + (size_t)src * 128 + hl * 8);
            float2 f0 = __bfloat1622float2(*(__nv_bfloat162*)&hv.x);
            float2 f1 = __bfloat1622float2(*(__nv_bfloat162*)&hv.y);
            float2 f2 = __bfloat1622float2(*(__nv_bfloat162*)&hv.z);
            float2 f3 = __bfloat1622float2(*(__nv_bfloat162*)&hv.w);
            a8[0] = fmaf(ws, f0.x, a8[0]); a8[1] = fmaf(ws, f0.y, a8[1]);
            a8[2] = fmaf(ws, f1.x, a8[2]); a8[3] = fmaf(ws, f1.y, a8[3]);
            a8[4] = fmaf(ws, f2.x, a8[4]); a8[5] = fmaf(ws, f2.y, a8[5]);
            a8[6] = fmaf(ws, f3.x, a8[6]); a8[7] = fmaf(ws, f3.y, a8[7]);
        }
        // merge the two half-accumulators (lanes L and L+16 hold the same columns)
#pragma unroll
        for (int j = 0; j < 8; j++) a8[j] += __shfl_xor_sync(0xffffffffu, a8[j], 16);
        if (half == 0) {
            __nv_bfloat162 q0 = __float22bfloat162_rn(make_float2(a8[0], a8[1]));
            __nv_bfloat162 q1 = __float22bfloat162_rn(make_float2(a8[2], a8[3]));
            __nv_bfloat162 q2 = __float22bfloat162_rn(make_float2(a8[4], a8[5]));
            __nv_bfloat162 q3 = __float22bfloat162_rn(make_float2(a8[6], a8[7]));
            uint4 ov;
            ov.x = *(uint32_t*)&q0; ov.y = *(uint32_t*)&q1;
            ov.z = *(uint32_t*)&q2; ov.w = *(uint32_t*)&q3;
            *(uint4*)(g_out1b + (size_t)gw * 128 + hl * 8) = ov;
        }
    } else {
        // ---- slow path (rare): 2-pass online softmax, 1 edge per iteration ----
        float4 acc = make_float4(0.f, 0.f, 0.f, 0.f);
        float m0 = -1e30f, m1 = -1e30f, m2 = -1e30f, m3 = -1e30f;
        float s0 = 0.f, s1 = 0.f, s2 = 0.f, s3 = 0.f;
        for (int j = row + lane; j < end; j += 32) {
            int src = __ldg(&g_srcs[j]);
            float4 a = g_as1[src];
            float e0 = lrelu(a.x + d4.x), e1 = lrelu(a.y + d4.y);
            float e2 = lrelu(a.z + d4.z), e3 = lrelu(a.w + d4.w);
            float n0 = fmaxf(m0, e0); s0 = s0 * __expf(m0 - n0) + __expf(e0 - n0); m0 = n0;
            float n1 = fmaxf(m1, e1); s1 = s1 * __expf(m1 - n1) + __expf(e1 - n1); m1 = n1;
            float n2 = fmaxf(m2, e2); s2 = s2 * __expf(m2 - n2) + __expf(e2 - n2); m2 = n2;
            float n3 = fmaxf(m3, e3); s3 = s3 * __expf(m3 - n3) + __expf(e3 - n3); m3 = n3;
        }
        float M0 = wmaxf(m0), M1 = wmaxf(m1), M2 = wmaxf(m2), M3 = wmaxf(m3);
        float i0 = 1.f / (wsumf(s0 * __expf(m0 - M0)) + 1e-16f);
        float i1 = 1.f / (wsumf(s1 * __expf(m1 - M1)) + 1e-16f);
        float i2 = 1.f / (wsumf(s2 * __expf(m2 - M2)) + 1e-16f);
        float i3 = 1.f / (wsumf(s3 * __expf(m3 - M3)) + 1e-16f);
        for (int cb = row; cb < end; cb += 32) {
            int rem = end - cb;
            int msrc = 0;
            float w0 = 0.f, w1 = 0.f, w2 = 0.f, w3 = 0.f;
            if (lane < rem) {
                msrc = __ldg(&g_srcs[cb + lane]);
                float4 a = g_as1[msrc];
                w0 = __expf(lrelu(a.x + d4.x) - M0) * i0;
                w1 = __expf(lrelu(a.y + d4.y) - M1) * i1;
                w2 = __expf(lrelu(a.z + d4.z) - M2) * i2;
                w3 = __expf(lrelu(a.w + d4.w) - M3) * i3;
            }
            int cnt = rem < 32 ? rem : 32;
            for (int e = 0; e < cnt; e++) {
                int   src = __shfl_sync(0xffffffffu, msrc, e);
                float b0  = __shfl_sync(0xffffffffu, w0, e);
                float b1v = __shfl_sync(0xffffffffu, w1, e);
                float b2v = __shfl_sync(0xffffffffu, w2, e);
                float b3  = __shfl_sync(0xffffffffu, w3, e);
                float wl = (lane & 8) ? b1v : b0;
                float wh = (lane & 8) ? b3 : b2v;
                float ws = (lane & 16) ? wh : wl;
                uint2 hv = *(const uint2*)(g_h1b + (size_t)src * 128 + lane * 4);
                float2 f0 = __bfloat1622float2(*(__nv_bfloat162*)&hv.x);
                float2 f1 = __bfloat1622float2(*(__nv_bfloat162*)&hv.y);
                acc.x = fmaf(ws, f0.x, acc.x);
                acc.y = fmaf(ws, f0.y, acc.y);
                acc.z = fmaf(ws, f1.x, acc.z);
                acc.w = fmaf(ws, f1.y, acc.w);
            }
        }
        __nv_bfloat162 o0 = __float22bfloat162_rn(make_float2(acc.x, acc.y));
        __nv_bfloat162 o1 = __float22bfloat162_rn(make_float2(acc.z, acc.w));
        uint2 ov;
        ov.x = *(uint32_t*)&o0;
        ov.y = *(uint32_t*)&o1;
        *(uint2*)(g_out1b + (size_t)gw * 128 + lane * 4) = ov;
    }
}

// ---------------- layer2: h2 = elu(out1+b1) @ W2, plus attention scores ----------------
__global__ void layer2_kernel(const float* __restrict__ W2, const float* __restrict__ b1,
                              const float* __restrict__ asrc2, const float* __restrict__ adst2, int N) {
    __shared__ float w2s[128 * 8];
    __shared__ float b1s[128];
    __shared__ float s2s[8], d2s[8];
    int tid = threadIdx.x;
    for (int i = tid; i < 1024; i += 256) w2s[i] = W2[i];
    if (tid < 128) b1s[tid] = b1[tid];
    if (tid < 8) { s2s[tid] = asrc2[tid]; d2s[tid] = adst2[tid]; }
    __syncthreads();
    int n = blockIdx.x * 256 + tid;
    if (n >= N) return;
    float acc[8];
#pragma unroll
    for (int c = 0; c < 8; c++) acc[c] = 0.f;
    const uint4* op = (const uint4*)&g_out1b[(size_t)n * 128];  // 8 bf16 per uint4
#pragma unroll 4
    for (int k8 = 0; k8 < 16; k8++) {
        uint4 v = op[k8];
        float2 f0 = __bfloat1622float2(*(__nv_bfloat162*)&v.x);
        float2 f1 = __bfloat1622float2(*(__nv_bfloat162*)&v.y);
        float2 f2 = __bfloat1622float2(*(__nv_bfloat162*)&v.z);
        float2 f3 = __bfloat1622float2(*(__nv_bfloat162*)&v.w);
        float vv[8] = {f0.x, f0.y, f1.x, f1.y, f2.x, f2.y, f3.x, f3.y};
#pragma unroll
        for (int j = 0; j < 8; j++) {
            int k = k8 * 8 + j;
            float tv = eluf(vv[j] + b1s[k]);
#pragma unroll
            for (int c = 0; c < 8; c++) acc[c] = fmaf(tv, w2s[k * 8 + c], acc[c]);
        }
    }
    ((float4*)&g_h2[n * 8])[0] = make_float4(acc[0], acc[1], acc[2], acc[3]);
    ((float4*)&g_h2[n * 8])[1] = make_float4(acc[4], acc[5], acc[6], acc[7]);
    float s = 0.f, d = 0.f;
#pragma unroll
    for (int c = 0; c < 8; c++) { s += acc[c] * s2s[c]; d += acc[c] * d2s[c]; }
    g_as2[n] = s;
    g_ad2[n] = d;
}

// ---------------- layer2 softmax + aggregation + final output (fused) ----------------
__global__ void agg2_final_kernel(const float* __restrict__ b2, const float* __restrict__ Wlin,
                                  const float* __restrict__ blin, float* __restrict__ out, int N) {
    int gw = (blockIdx.x * blockDim.x + threadIdx.x) >> 5;
    int lane = threadIdx.x & 31;
    if (gw >= N) return;
    int row = g_rowstart[gw], end = g_rowstart[gw + 1];
    int deg = end - row;
    float dd = g_ad2[gw];
    float a0 = 0.f, a1 = 0.f, a2 = 0.f, a3 = 0.f, a4 = 0.f, a5 = 0.f, a6 = 0.f, a7 = 0.f;

    if (deg <= 32) {
        int msrc = 0;
        float e = -1e30f;
        if (lane < deg) {
            msrc = __ldg(&g_srcs[row + lane]);
            e = lrelu(g_as2[msrc] + dd);
        }
        float M = wmaxf(e);
        float t = (lane < deg) ? __expf(e - M) : 0.f;
        float w = t / (wsumf(t) + 1e-16f);
        if (lane < deg) {
            const float4* hp = (const float4*)(g_h2 + (size_t)msrc * 8);
            float4 v0 = hp[0], v1 = hp[1];
            a0 = w * v0.x; a1 = w * v0.y; a2 = w * v0.z; a3 = w * v0.w;
            a4 = w * v1.x; a5 = w * v1.y; a6 = w * v1.z; a7 = w * v1.w;
        }
    } else {
        float m = -1e30f, s = 0.f;
        for (int j = row + lane; j < end; j += 32) {
            int src = __ldg(&g_srcs[j]);
            float e = lrelu(g_as2[src] + dd);
            float nm = fmaxf(m, e);
            s = s * __expf(m - nm) + __expf(e - nm);
            m = nm;
        }
        float M = wmaxf(m);
        float inv = 1.f / (wsumf(s * __expf(m - M)) + 1e-16f);
        for (int j = row + lane; j < end; j += 32) {
            int src = __ldg(&g_srcs[j]);
            float w = __expf(lrelu(g_as2[src] + dd) - M) * inv;
            const float4* hp = (const float4*)(g_h2 + (size_t)src * 8);
            float4 v0 = hp[0], v1 = hp[1];
            a0 = fmaf(w, v0.x, a0); a1 = fmaf(w, v0.y, a1);
            a2 = fmaf(w, v0.z, a2); a3 = fmaf(w, v0.w, a3);
            a4 = fmaf(w, v1.x, a4); a5 = fmaf(w, v1.y, a5);
            a6 = fmaf(w, v1.z, a6); a7 = fmaf(w, v1.w, a7);
        }
    }
    a0 = wsumf(a0); a1 = wsumf(a1); a2 = wsumf(a2); a3 = wsumf(a3);
    a4 = wsumf(a4); a5 = wsumf(a5); a6 = wsumf(a6); a7 = wsumf(a7);
    if (lane == 0) {
        float o[8] = {a0, a1, a2, a3, a4, a5, a6, a7};
        float y = __ldg(&blin[0]);
#pragma unroll
        for (int j = 0; j < 8; j++) {
            float t = eluf(o[j] + __ldg(&b2[j]));
            y = fmaf(t, __ldg(&Wlin[j]), y);
        }
        out[gw] = 1.f / (1.f + __expf(-y));
    }
}

// ---------------- launch ----------------
extern "C" void kernel_launch(void* const* d_in, const int* in_sizes, int n_in,
                              void* d_out, int out_size) {
    const float* x    = (const float*)d_in[0];
    const int*   ei   = (const int*)d_in[1];
    // d_in[2] edge_attr unused
    const float* W1   = (const float*)d_in[3];
    const float* as1  = (const float*)d_in[4];
    const float* ad1  = (const float*)d_in[5];
    const float* b1   = (const float*)d_in[6];
    const float* W2   = (const float*)d_in[7];
    const float* as2w = (const float*)d_in[8];
    const float* ad2w = (const float*)d_in[9];
    const float* b2   = (const float*)d_in[10];
    const float* Wlin = (const float*)d_in[11];
    const float* blin = (const float*)d_in[12];
    float* out = (float*)d_out;

    int N = in_sizes[0] / 128;
    int E = in_sizes[1] / 2;
    int Etot = E + N;
    int nch = (N + SCAN_CHUNK - 1) / SCAN_CHUNK;
    const int TB = 256;
    const int SMEM_GEMM = (256 * 132 + 128 * 136) * 4;  // 204800 B

    cudaFuncSetAttribute(gemm1_kernel, cudaFuncAttributeMaxDynamicSharedMemorySize, SMEM_GEMM);

    // Fork: CSR build (ei only) concurrent with gemm1 (x/W1 only).
    cudaStream_t s2;
    cudaStreamCreate(&s2);
    cudaEvent_t evFork, evJoin;
    cudaEventCreateWithFlags(&evFork, cudaEventDisableTiming);
    cudaEventCreateWithFlags(&evJoin, cudaEventDisableTiming);

    cudaEventRecord(evFork, 0);
    cudaStreamWaitEvent(s2, evFork, 0);

    zero_deg_kernel<<<(N + TB - 1) / TB, TB, 0, s2>>>(N);
    count_kernel<<<(Etot + TB - 1) / TB, TB, 0, s2>>>(ei, E, Etot);
    scan1_kernel<<<nch, SCAN_CHUNK, 0, s2>>>(N);
    scan2_kernel<<<1, SCAN_CHUNK, 0, s2>>>(nch);
    scan3_kernel<<<nch, SCAN_CHUNK, 0, s2>>>(N, Etot);
    fill_kernel<<<(Etot + TB - 1) / TB, TB, 0, s2>>>(ei, E, Etot);
    cudaEventRecord(evJoin, s2);

    gemm1_kernel<<<(N + 255) / 256, 512, SMEM_GEMM>>>(x, W1, as1, ad1, N);

    cudaStreamWaitEvent(0, evJoin, 0);
    agg1_kernel<<<(N * 32 + TB - 1) / TB, TB>>>(N);
    layer2_kernel<<<(N + TB - 1) / TB, TB>>>(W2, b1, as2w, ad2w, N);
    agg2_final_kernel<<<(N * 32 + TB - 1) / TB, TB>>>(b2, Wlin, blin, out, N);

    cudaEventDestroy(evFork);
    cudaEventDestroy(evJoin);
    cudaStreamDestroy(s2);
}

// round 9
// speedup vs baseline: 1.3308x; 1.0343x over previous
#include <cuda_runtime.h>
#include <cuda_bf16.h>
#include <math.h>
#include <stdint.h>

#define NMAX 100000
#define EMAX 1600000
#define ETMAX (EMAX + NMAX)
#define SCAN_CHUNK 512
#define NCHMAX 256

// ---------------- scratch (device globals; no allocation allowed) ----------------
__device__ __nv_bfloat16 g_h1b[NMAX * 128];   // layer1 features, bf16 (25.6 MB)
__device__ __nv_bfloat16 g_out1b[NMAX * 128]; // layer1 aggregated, bf16 (25.6 MB)
__device__ float4 g_as1[NMAX];                // alpha_src layer1 (4 heads)
__device__ float4 g_ad1[NMAX];                // alpha_dst layer1
__device__ float  g_h2[NMAX * 8];
__device__ float  g_as2[NMAX];
__device__ float  g_ad2[NMAX];
// CSR scratch
__device__ int    g_deg[NMAX];
__device__ int    g_rowstart[NMAX + 1];
__device__ int    g_eslot[ETMAX];             // per-edge slot within its dst row
__device__ int    g_srcs[ETMAX];
__device__ int    g_csum[NCHMAX];

// ---------------- helpers ----------------
__device__ __forceinline__ float lrelu(float v) { return v > 0.f ? v : 0.2f * v; }
__device__ __forceinline__ float eluf(float v)  { return v > 0.f ? v : (__expf(v) - 1.f); }
__device__ __forceinline__ float wmaxf(float v) {
#pragma unroll
    for (int o = 16; o; o >>= 1) v = fmaxf(v, __shfl_xor_sync(0xffffffffu, v, o));
    return v;
}
__device__ __forceinline__ float wsumf(float v) {
#pragma unroll
    for (int o = 16; o; o >>= 1) v += __shfl_xor_sync(0xffffffffu, v, o);
    return v;
}
__device__ __forceinline__ uint32_t f2tf32(float f) {
    uint32_t r; asm("cvt.rna.tf32.f32 %0, %1;" : "=r"(r) : "f"(f)); return r;
}
__device__ __forceinline__ void mma_tf32(float& d0, float& d1, float& d2, float& d3,
                                         uint32_t a0, uint32_t a1, uint32_t a2, uint32_t a3,
                                         uint32_t b0, uint32_t b1) {
    asm("mma.sync.aligned.m16n8k8.row.col.f32.tf32.tf32.f32 "
        "{%0,%1,%2,%3}, {%4,%5,%6,%7}, {%8,%9}, {%0,%1,%2,%3};"
        : "+f"(d0), "+f"(d1), "+f"(d2), "+f"(d3)
        : "r"(a0), "r"(a1), "r"(a2), "r"(a3), "r"(b0), "r"(b1));
}

// ---------------- CSR build ----------------
__global__ void zero_deg_kernel(int N) {
    int i = blockIdx.x * blockDim.x + threadIdx.x;
    if (i < N) g_deg[i] = 0;
}

__global__ void count_kernel(const int* __restrict__ ei, int E, int Etot) {
    int idx = blockIdx.x * blockDim.x + threadIdx.x;
    if (idx >= Etot) return;
    int dst = (idx < E) ? ei[E + idx] : (idx - E);
    int slot = atomicAdd(&g_deg[dst], 1);
    g_eslot[idx] = slot;   // coalesced; reused by fill to avoid a second scattered atomic
}

__global__ void scan1_kernel(int N) {
    __shared__ int sh[SCAN_CHUNK];
    int t = threadIdx.x;
    int i = blockIdx.x * SCAN_CHUNK + t;
    sh[t] = (i < N) ? g_deg[i] : 0;
    __syncthreads();
#pragma unroll
    for (int s = SCAN_CHUNK / 2; s > 0; s >>= 1) {
        if (t < s) sh[t] += sh[t + s];
        __syncthreads();
    }
    if (t == 0) g_csum[blockIdx.x] = sh[0];
}

// fused: every block redundantly exclusive-scans the chunk sums, then does its chunk
__global__ void scan3_fused_kernel(int N, int Etot, int nch) {
    __shared__ int chs[NCHMAX];
    __shared__ int sh[SCAN_CHUNK];
    int t = threadIdx.x;
    if (t < NCHMAX) chs[t] = (t < nch) ? g_csum[t] : 0;
    __syncthreads();
#pragma unroll
    for (int off = 1; off < NCHMAX; off <<= 1) {
        int add = 0;
        if (t < NCHMAX && t >= off) add = chs[t - off];
        __syncthreads();
        if (t < NCHMAX) chs[t] += add;
        __syncthreads();
    }
    int boff = (blockIdx.x == 0) ? 0 : chs[blockIdx.x - 1];
    int i = blockIdx.x * SCAN_CHUNK + t;
    int v = (i < N) ? g_deg[i] : 0;
    sh[t] = v;
    __syncthreads();
#pragma unroll
    for (int off = 1; off < SCAN_CHUNK; off <<= 1) {
        int add = (t >= off) ? sh[t - off] : 0;
        __syncthreads();
        sh[t] += add;
        __syncthreads();
    }
    if (i < N) g_rowstart[i] = sh[t] - v + boff;
    if (blockIdx.x == 0 && t == 0) g_rowstart[N] = Etot;
}

__global__ void fill_kernel(const int* __restrict__ ei, int E, int Etot) {
    int idx = blockIdx.x * blockDim.x + threadIdx.x;
    if (idx >= Etot) return;
    int src, dst;
    if (idx < E) { src = ei[idx]; dst = ei[E + idx]; } else { src = dst = idx - E; }
    g_srcs[g_rowstart[dst] + g_eslot[idx]] = src;  // no atomic: slot precomputed in count
}

// ---------------- layer1 GEMM (tf32 tensor cores) + fused alpha epilogue ----------------
__global__ __launch_bounds__(512) void gemm1_kernel(
    const float* __restrict__ x, const float* __restrict__ W,
    const float* __restrict__ asrc, const float* __restrict__ adst, int N) {
    extern __shared__ float sm[];
    float* xs = sm;               // 256*132
    float* wk = sm + 256 * 132;   // 128*136
    int tid = threadIdx.x;
    int base = blockIdx.x * 256;

    for (int i = tid; i < 4096; i += 512) {
        int k = i >> 5, c4 = i & 31;
        float4 v = ((const float4*)W)[i];
        float4 o;
        o.x = __uint_as_float(f2tf32(v.x));
        o.y = __uint_as_float(f2tf32(v.y));
        o.z = __uint_as_float(f2tf32(v.z));
        o.w = __uint_as_float(f2tf32(v.w));
        *(float4*)&wk[k * 136 + c4 * 4] = o;
    }
    for (int i = tid; i < 8192; i += 512) {
        int r = i >> 5, c4 = i & 31;
        int gr = base + r;
        float4 v = make_float4(0.f, 0.f, 0.f, 0.f);
        if (gr < N) v = ((const float4*)x)[gr * 32 + c4];
        float4 o;
        o.x = __uint_as_float(f2tf32(v.x));
        o.y = __uint_as_float(f2tf32(v.y));
        o.z = __uint_as_float(f2tf32(v.z));
        o.w = __uint_as_float(f2tf32(v.w));
        *(float4*)&xs[r * 132 + c4 * 4] = o;
    }
    __syncthreads();

    int w = tid >> 5, lane = tid & 31;
    int tg = lane & 3, grp = lane >> 2;
    int r0 = w * 16;

    float acc[16][4];
#pragma unroll
    for (int j = 0; j < 16; j++)
#pragma unroll
        for (int q = 0; q < 4; q++) acc[j][q] = 0.f;

#pragma unroll 4
    for (int ks = 0; ks < 16; ks++) {
        int k0 = ks * 8;
        const float* ax = xs + (r0 + grp) * 132 + k0 + tg;
        uint32_t a0 = __float_as_uint(ax[0]);
        uint32_t a1 = __float_as_uint(ax[8 * 132]);
        uint32_t a2 = __float_as_uint(ax[4]);
        uint32_t a3 = __float_as_uint(ax[8 * 132 + 4]);
        const float* bx = wk + (k0 + tg) * 136 + grp;
#pragma unroll
        for (int j = 0; j < 16; j++) {
            uint32_t b0 = __float_as_uint(bx[8 * j]);
            uint32_t b1 = __float_as_uint(bx[4 * 136 + 8 * j]);
            mma_tf32(acc[j][0], acc[j][1], acc[j][2], acc[j][3], a0, a1, a2, a3, b0, b1);
        }
    }

    // ---- epilogue: store h1 (bf16) + fused alpha dot products ----
    int gr0 = base + r0 + grp;
    int gr8 = gr0 + 8;
    float s_r0[4] = {0, 0, 0, 0}, s_r8[4] = {0, 0, 0, 0};
    float d_r0[4] = {0, 0, 0, 0}, d_r8[4] = {0, 0, 0, 0};
#pragma unroll
    for (int j = 0; j < 16; j++) {
        int c = 8 * j + 2 * tg;
        int h = j >> 2;
        float A0 = __ldg(&asrc[c]), A1 = __ldg(&asrc[c + 1]);
        float D0 = __ldg(&adst[c]), D1 = __ldg(&adst[c + 1]);
        s_r0[h] = fmaf(acc[j][0], A0, fmaf(acc[j][1], A1, s_r0[h]));
        s_r8[h] = fmaf(acc[j][2], A0, fmaf(acc[j][3], A1, s_r8[h]));
        d_r0[h] = fmaf(acc[j][0], D0, fmaf(acc[j][1], D1, d_r0[h]));
        d_r8[h] = fmaf(acc[j][2], D0, fmaf(acc[j][3], D1, d_r8[h]));
        if (gr0 < N)
            *(__nv_bfloat162*)&g_h1b[(size_t)gr0 * 128 + c] =
                __float22bfloat162_rn(make_float2(acc[j][0], acc[j][1]));
        if (gr8 < N)
            *(__nv_bfloat162*)&g_h1b[(size_t)gr8 * 128 + c] =
                __float22bfloat162_rn(make_float2(acc[j][2], acc[j][3]));
    }
#pragma unroll
    for (int h = 0; h < 4; h++) {
        s_r0[h] += __shfl_xor_sync(0xffffffffu, s_r0[h], 1);
        s_r0[h] += __shfl_xor_sync(0xffffffffu, s_r0[h], 2);
        s_r8[h] += __shfl_xor_sync(0xffffffffu, s_r8[h], 1);
        s_r8[h] += __shfl_xor_sync(0xffffffffu, s_r8[h], 2);
        d_r0[h] += __shfl_xor_sync(0xffffffffu, d_r0[h], 1);
        d_r0[h] += __shfl_xor_sync(0xffffffffu, d_r0[h], 2);
        d_r8[h] += __shfl_xor_sync(0xffffffffu, d_r8[h], 1);
        d_r8[h] += __shfl_xor_sync(0xffffffffu, d_r8[h], 2);
    }
    if (tg == 0) {
        if (gr0 < N) {
            g_as1[gr0] = make_float4(s_r0[0], s_r0[1], s_r0[2], s_r0[3]);
            g_ad1[gr0] = make_float4(d_r0[0], d_r0[1], d_r0[2], d_r0[3]);
        }
        if (gr8 < N) {
            g_as1[gr8] = make_float4(s_r8[0], s_r8[1], s_r8[2], s_r8[3]);
            g_ad1[gr8] = make_float4(d_r8[0], d_r8[1], d_r8[2], d_r8[3]);
        }
    }
}

// ---------------- layer1 fused softmax + aggregation: warp per dst ----------------
__global__ void agg1_kernel(int N) {
    __shared__ float4 swsel[8][32];   // per-warp: per-edge weights (w0..w3) as float4
    __shared__ int    sssrc[8][32];   // per-warp: per-edge src ids
    int gw = (blockIdx.x * blockDim.x + threadIdx.x) >> 5;
    int lane = threadIdx.x & 31;
    int wip = (threadIdx.x >> 5) & 7;
    if (gw >= N) return;
    int row = g_rowstart[gw], end = g_rowstart[gw + 1];
    int deg = end - row;
    float4 d4 = g_ad1[gw];

    if (deg <= 32) {
        // ---- fast path: weights staged in smem, 2 edges per iteration ----
        int msrc = 0;
        float e0 = -1e30f, e1 = -1e30f, e2 = -1e30f, e3 = -1e30f;
        if (lane < deg) {
            msrc = __ldg(&g_srcs[row + lane]);
            float4 a = g_as1[msrc];
            e0 = lrelu(a.x + d4.x); e1 = lrelu(a.y + d4.y);
            e2 = lrelu(a.z + d4.z); e3 = lrelu(a.w + d4.w);
        }
        float M0 = wmaxf(e0), M1 = wmaxf(e1), M2 = wmaxf(e2), M3 = wmaxf(e3);
        float t0 = (lane < deg) ? __expf(e0 - M0) : 0.f;
        float t1 = (lane < deg) ? __expf(e1 - M1) : 0.f;
        float t2 = (lane < deg) ? __expf(e2 - M2) : 0.f;
        float t3 = (lane < deg) ? __expf(e3 - M3) : 0.f;
        float w0 = t0 / (wsumf(t0) + 1e-16f);
        float w1 = t1 / (wsumf(t1) + 1e-16f);
        float w2 = t2 / (wsumf(t2) + 1e-16f);
        float w3 = t3 / (wsumf(t3) + 1e-16f);
        swsel[wip][lane] = make_float4(w0, w1, w2, w3);  // STS.128, conflict-free
        sssrc[wip][lane] = msrc;
        __syncwarp();

        // lanes 0-15 -> edge e, lanes 16-31 -> edge e+1; each lane covers 8 columns (16B)
        int half = lane >> 4;
        int hl = lane & 15;
        int head = hl >> 2;
        const float* wselp = (const float*)&swsel[wip][0];
        float a8[8];
#pragma unroll
        for (int j = 0; j < 8; j++) a8[j] = 0.f;

#pragma unroll 4
        for (int e = 0; e < deg; e += 2) {
            int idx = e + half;                    // idx==deg lanes carry w=0
            int   src = sssrc[wip][idx];           // LDS broadcast (2 addrs/warp)
            float ws  = wselp[idx * 4 + head];     // LDS, conflict-free banks
            uint4 hv = *(const uint4*)(g_h1b + (size_t)src * 128 + hl * 8);
            float2 f0 = __bfloat1622float2(*(__nv_bfloat162*)&hv.x);
            float2 f1 = __bfloat1622float2(*(__nv_bfloat162*)&hv.y);
            float2 f2 = __bfloat1622float2(*(__nv_bfloat162*)&hv.z);
            float2 f3 = __bfloat1622float2(*(__nv_bfloat162*)&hv.w);
            a8[0] = fmaf(ws, f0.x, a8[0]); a8[1] = fmaf(ws, f0.y, a8[1]);
            a8[2] = fmaf(ws, f1.x, a8[2]); a8[3] = fmaf(ws, f1.y, a8[3]);
            a8[4] = fmaf(ws, f2.x, a8[4]); a8[5] = fmaf(ws, f2.y, a8[5]);
            a8[6] = fmaf(ws, f3.x, a8[6]); a8[7] = fmaf(ws, f3.y, a8[7]);
        }
        // merge two half-accumulators (lanes L and L+16 hold same columns)
#pragma unroll
        for (int j = 0; j < 8; j++) a8[j] += __shfl_xor_sync(0xffffffffu, a8[j], 16);
        if (half == 0) {
            __nv_bfloat162 q0 = __float22bfloat162_rn(make_float2(a8[0], a8[1]));
            __nv_bfloat162 q1 = __float22bfloat162_rn(make_float2(a8[2], a8[3]));
            __nv_bfloat162 q2 = __float22bfloat162_rn(make_float2(a8[4], a8[5]));
            __nv_bfloat162 q3 = __float22bfloat162_rn(make_float2(a8[6], a8[7]));
            uint4 ov;
            ov.x = *(uint32_t*)&q0; ov.y = *(uint32_t*)&q1;
            ov.z = *(uint32_t*)&q2; ov.w = *(uint32_t*)&q3;
            *(uint4*)(g_out1b + (size_t)gw * 128 + hl * 8) = ov;
        }
    } else {
        // ---- slow path (rare): 2-pass online softmax ----
        float4 acc = make_float4(0.f, 0.f, 0.f, 0.f);
        float m0 = -1e30f, m1 = -1e30f, m2 = -1e30f, m3 = -1e30f;
        float s0 = 0.f, s1 = 0.f, s2 = 0.f, s3 = 0.f;
        for (int j = row + lane; j < end; j += 32) {
            int src = __ldg(&g_srcs[j]);
            float4 a = g_as1[src];
            float e0 = lrelu(a.x + d4.x), e1 = lrelu(a.y + d4.y);
            float e2 = lrelu(a.z + d4.z), e3 = lrelu(a.w + d4.w);
            float n0 = fmaxf(m0, e0); s0 = s0 * __expf(m0 - n0) + __expf(e0 - n0); m0 = n0;
            float n1 = fmaxf(m1, e1); s1 = s1 * __expf(m1 - n1) + __expf(e1 - n1); m1 = n1;
            float n2 = fmaxf(m2, e2); s2 = s2 * __expf(m2 - n2) + __expf(e2 - n2); m2 = n2;
            float n3 = fmaxf(m3, e3); s3 = s3 * __expf(m3 - n3) + __expf(e3 - n3); m3 = n3;
        }
        float M0 = wmaxf(m0), M1 = wmaxf(m1), M2 = wmaxf(m2), M3 = wmaxf(m3);
        float i0 = 1.f / (wsumf(s0 * __expf(m0 - M0)) + 1e-16f);
        float i1 = 1.f / (wsumf(s1 * __expf(m1 - M1)) + 1e-16f);
        float i2 = 1.f / (wsumf(s2 * __expf(m2 - M2)) + 1e-16f);
        float i3 = 1.f / (wsumf(s3 * __expf(m3 - M3)) + 1e-16f);
        for (int cb = row; cb < end; cb += 32) {
            int rem = end - cb;
            int msrc = 0;
            float w0 = 0.f, w1 = 0.f, w2 = 0.f, w3 = 0.f;
            if (lane < rem) {
                msrc = __ldg(&g_srcs[cb + lane]);
                float4 a = g_as1[msrc];
                w0 = __expf(lrelu(a.x + d4.x) - M0) * i0;
                w1 = __expf(lrelu(a.y + d4.y) - M1) * i1;
                w2 = __expf(lrelu(a.z + d4.z) - M2) * i2;
                w3 = __expf(lrelu(a.w + d4.w) - M3) * i3;
            }
            int cnt = rem < 32 ? rem : 32;
            for (int e = 0; e < cnt; e++) {
                int   src = __shfl_sync(0xffffffffu, msrc, e);
                float b0  = __shfl_sync(0xffffffffu, w0, e);
                float b1v = __shfl_sync(0xffffffffu, w1, e);
                float b2v = __shfl_sync(0xffffffffu, w2, e);
                float b3  = __shfl_sync(0xffffffffu, w3, e);
                float wl = (lane & 8) ? b1v : b0;
                float wh = (lane & 8) ? b3 : b2v;
                float ws = (lane & 16) ? wh : wl;
                uint2 hv = *(const uint2*)(g_h1b + (size_t)src * 128 + lane * 4);
                float2 f0 = __bfloat1622float2(*(__nv_bfloat162*)&hv.x);
                float2 f1 = __bfloat1622float2(*(__nv_bfloat162*)&hv.y);
                acc.x = fmaf(ws, f0.x, acc.x);
                acc.y = fmaf(ws, f0.y, acc.y);
                acc.z = fmaf(ws, f1.x, acc.z);
                acc.w = fmaf(ws, f1.y, acc.w);
            }
        }
        __nv_bfloat162 o0 = __float22bfloat162_rn(make_float2(acc.x, acc.y));
        __nv_bfloat162 o1 = __float22bfloat162_rn(make_float2(acc.z, acc.w));
        uint2 ov;
        ov.x = *(uint32_t*)&o0;
        ov.y = *(uint32_t*)&o1;
        *(uint2*)(g_out1b + (size_t)gw * 128 + lane * 4) = ov;
    }
}

// ---------------- layer2: h2 = elu(out1+b1) @ W2, plus attention scores ----------------
__global__ void layer2_kernel(const float* __restrict__ W2, const float* __restrict__ b1,
                              const float* __restrict__ asrc2, const float* __restrict__ adst2, int N) {
    __shared__ float w2s[128 * 8];
    __shared__ float b1s[128];
    __shared__ float s2s[8], d2s[8];
    int tid = threadIdx.x;
    for (int i = tid; i < 1024; i += 256) w2s[i] = W2[i];
    if (tid < 128) b1s[tid] = b1[tid];
    if (tid < 8) { s2s[tid] = asrc2[tid]; d2s[tid] = adst2[tid]; }
    __syncthreads();
    int n = blockIdx.x * 256 + tid;
    if (n >= N) return;
    float acc[8];
#pragma unroll
    for (int c = 0; c < 8; c++) acc[c] = 0.f;
    const uint4* op = (const uint4*)&g_out1b[(size_t)n * 128];
#pragma unroll 4
    for (int k8 = 0; k8 < 16; k8++) {
        uint4 v = op[k8];
        float2 f0 = __bfloat1622float2(*(__nv_bfloat162*)&v.x);
        float2 f1 = __bfloat1622float2(*(__nv_bfloat162*)&v.y);
        float2 f2 = __bfloat1622float2(*(__nv_bfloat162*)&v.z);
        float2 f3 = __bfloat1622float2(*(__nv_bfloat162*)&v.w);
        float vv[8] = {f0.x, f0.y, f1.x, f1.y, f2.x, f2.y, f3.x, f3.y};
#pragma unroll
        for (int j = 0; j < 8; j++) {
            int k = k8 * 8 + j;
            float tv = eluf(vv[j] + b1s[k]);
#pragma unroll
            for (int c = 0; c < 8; c++) acc[c] = fmaf(tv, w2s[k * 8 + c], acc[c]);
        }
    }
    ((float4*)&g_h2[n * 8])[0] = make_float4(acc[0], acc[1], acc[2], acc[3]);
    ((float4*)&g_h2[n * 8])[1] = make_float4(acc[4], acc[5], acc[6], acc[7]);
    float s = 0.f, d = 0.f;
#pragma unroll
    for (int c = 0; c < 8; c++) { s += acc[c] * s2s[c]; d += acc[c] * d2s[c]; }
    g_as2[n] = s;
    g_ad2[n] = d;
}

// ---------------- layer2 softmax + aggregation + final output (fused) ----------------
__global__ void agg2_final_kernel(const float* __restrict__ b2, const float* __restrict__ Wlin,
                                  const float* __restrict__ blin, float* __restrict__ out, int N) {
    int gw = (blockIdx.x * blockDim.x + threadIdx.x) >> 5;
    int lane = threadIdx.x & 31;
    if (gw >= N) return;
    int row = g_rowstart[gw], end = g_rowstart[gw + 1];
    int deg = end - row;
    float dd = g_ad2[gw];
    float a0 = 0.f, a1 = 0.f, a2 = 0.f, a3 = 0.f, a4 = 0.f, a5 = 0.f, a6 = 0.f, a7 = 0.f;

    if (deg <= 32) {
        int msrc = 0;
        float e = -1e30f;
        if (lane < deg) {
            msrc = __ldg(&g_srcs[row + lane]);
            e = lrelu(g_as2[msrc] + dd);
        }
        float M = wmaxf(e);
        float t = (lane < deg) ? __expf(e - M) : 0.f;
        float w = t / (wsumf(t) + 1e-16f);
        if (lane < deg) {
            const float4* hp = (const float4*)(g_h2 + (size_t)msrc * 8);
            float4 v0 = hp[0], v1 = hp[1];
            a0 = w * v0.x; a1 = w * v0.y; a2 = w * v0.z; a3 = w * v0.w;
            a4 = w * v1.x; a5 = w * v1.y; a6 = w * v1.z; a7 = w * v1.w;
        }
    } else {
        float m = -1e30f, s = 0.f;
        for (int j = row + lane; j < end; j += 32) {
            int src = __ldg(&g_srcs[j]);
            float e = lrelu(g_as2[src] + dd);
            float nm = fmaxf(m, e);
            s = s * __expf(m - nm) + __expf(e - nm);
            m = nm;
        }
        float M = wmaxf(m);
        float inv = 1.f / (wsumf(s * __expf(m - M)) + 1e-16f);
        for (int j = row + lane; j < end; j += 32) {
            int src = __ldg(&g_srcs[j]);
            float w = __expf(lrelu(g_as2[src] + dd) - M) * inv;
            const float4* hp = (const float4*)(g_h2 + (size_t)src * 8);
            float4 v0 = hp[0], v1 = hp[1];
            a0 = fmaf(w, v0.x, a0); a1 = fmaf(w, v0.y, a1);
            a2 = fmaf(w, v0.z, a2); a3 = fmaf(w, v0.w, a3);
            a4 = fmaf(w, v1.x, a4); a5 = fmaf(w, v1.y, a5);
            a6 = fmaf(w, v1.z, a6); a7 = fmaf(w, v1.w, a7);
        }
    }
    a0 = wsumf(a0); a1 = wsumf(a1); a2 = wsumf(a2); a3 = wsumf(a3);
    a4 = wsumf(a4); a5 = wsumf(a5); a6 = wsumf(a6); a7 = wsumf(a7);
    if (lane == 0) {
        float o[8] = {a0, a1, a2, a3, a4, a5, a6, a7};
        float y = __ldg(&blin[0]);
#pragma unroll
        for (int j = 0; j < 8; j++) {
            float t = eluf(o[j] + __ldg(&b2[j]));
            y = fmaf(t, __ldg(&Wlin[j]), y);
        }
        out[gw] = 1.f / (1.f + __expf(-y));
    }
}

// ---------------- launch ----------------
extern "C" void kernel_launch(void* const* d_in, const int* in_sizes, int n_in,
                              void* d_out, int out_size) {
    const float* x    = (const float*)d_in[0];
    const int*   ei   = (const int*)d_in[1];
    // d_in[2] edge_attr unused
    const float* W1   = (const float*)d_in[3];
    const float* as1  = (const float*)d_in[4];
    const float* ad1  = (const float*)d_in[5];
    const float* b1   = (const float*)d_in[6];
    const float* W2   = (const float*)d_in[7];
    const float* as2w = (const float*)d_in[8];
    const float* ad2w = (const float*)d_in[9];
    const float* b2   = (const float*)d_in[10];
    const float* Wlin = (const float*)d_in[11];
    const float* blin = (const float*)d_in[12];
    float* out = (float*)d_out;

    int N = in_sizes[0] / 128;
    int E = in_sizes[1] / 2;
    int Etot = E + N;
    int nch = (N + SCAN_CHUNK - 1) / SCAN_CHUNK;
    const int TB = 256;
    const int SMEM_GEMM = (256 * 132 + 128 * 136) * 4;  // 204800 B

    cudaFuncSetAttribute(gemm1_kernel, cudaFuncAttributeMaxDynamicSharedMemorySize, SMEM_GEMM);

    // Fork: CSR build (ei only) concurrent with gemm1 (x/W1 only).
    cudaStream_t s2;
    cudaStreamCreate(&s2);
    cudaEvent_t evFork, evJoin;
    cudaEventCreateWithFlags(&evFork, cudaEventDisableTiming);
    cudaEventCreateWithFlags(&evJoin, cudaEventDisableTiming);

    cudaEventRecord(evFork, 0);
    cudaStreamWaitEvent(s2, evFork, 0);

    zero_deg_kernel<<<(N + TB - 1) / TB, TB, 0, s2>>>(N);
    count_kernel<<<(Etot + TB - 1) / TB, TB, 0, s2>>>(ei, E, Etot);
    scan1_kernel<<<nch, SCAN_CHUNK, 0, s2>>>(N);
    scan3_fused_kernel<<<nch, SCAN_CHUNK, 0, s2>>>(N, Etot, nch);
    fill_kernel<<<(Etot + TB - 1) / TB, TB, 0, s2>>>(ei, E, Etot);
    cudaEventRecord(evJoin, s2);

    gemm1_kernel<<<(N + 255) / 256, 512, SMEM_GEMM>>>(x, W1, as1, ad1, N);

    cudaStreamWaitEvent(0, evJoin, 0);
    agg1_kernel<<<(N * 32 + TB - 1) / TB, TB>>>(N);
    layer2_kernel<<<(N + TB - 1) / TB, TB>>>(W2, b1, as2w, ad2w, N);
    agg2_final_kernel<<<(N * 32 + TB - 1) / TB, TB>>>(b2, Wlin, blin, out, N);

    cudaEventDestroy(evFork);
    cudaEventDestroy(evJoin);
    cudaStreamDestroy(s2);
}

// round 11
// speedup vs baseline: 1.4894x; 1.1191x over previous
#include <cuda_runtime.h>
#include <cuda_bf16.h>
#include <math.h>
#include <stdint.h>

#define NMAX 100000
#define EMAX 1600000
#define ETMAX (EMAX + NMAX)
#define SCAN_CHUNK 512
#define NCHMAX 256

// ---------------- scratch (device globals; no allocation allowed) ----------------
__device__ __nv_bfloat16 g_h1b[NMAX * 128];   // layer1 features, bf16 (25.6 MB)
__device__ __nv_bfloat16 g_out1b[NMAX * 128]; // layer1 aggregated, bf16 (25.6 MB)
__device__ float4 g_as1[NMAX];                // alpha_src layer1 (4 heads)
__device__ float4 g_ad1[NMAX];                // alpha_dst layer1
__device__ float  g_h2[NMAX * 8];
__device__ float  g_as2[NMAX];
__device__ float  g_ad2[NMAX];
// CSR scratch
__device__ int    g_deg[NMAX];
__device__ int    g_rowstart[NMAX + 1];
__device__ int    g_eslot[ETMAX];             // per-edge slot within its dst row
__device__ int    g_srcs[ETMAX];
__device__ int    g_csum[NCHMAX];

// ---------------- helpers ----------------
__device__ __forceinline__ float lrelu(float v) { return v > 0.f ? v : 0.2f * v; }
__device__ __forceinline__ float eluf(float v)  { return v > 0.f ? v : (__expf(v) - 1.f); }
__device__ __forceinline__ float wsumf(float v) {
#pragma unroll
    for (int o = 16; o; o >>= 1) v += __shfl_xor_sync(0xffffffffu, v, o);
    return v;
}
__device__ __forceinline__ uint32_t f2tf32(float f) {
    uint32_t r; asm("cvt.rna.tf32.f32 %0, %1;" : "=r"(r) : "f"(f)); return r;
}
__device__ __forceinline__ void mma_tf32(float& d0, float& d1, float& d2, float& d3,
                                         uint32_t a0, uint32_t a1, uint32_t a2, uint32_t a3,
                                         uint32_t b0, uint32_t b1) {
    asm("mma.sync.aligned.m16n8k8.row.col.f32.tf32.tf32.f32 "
        "{%0,%1,%2,%3}, {%4,%5,%6,%7}, {%8,%9}, {%0,%1,%2,%3};"
        : "+f"(d0), "+f"(d1), "+f"(d2), "+f"(d3)
        : "r"(a0), "r"(a1), "r"(a2), "r"(a3), "r"(b0), "r"(b1));
}

// ---------------- CSR build ----------------
__global__ void zero_deg_kernel(int N) {
    int i = blockIdx.x * blockDim.x + threadIdx.x;
    if (i < N) g_deg[i] = 0;
}

__global__ void count_kernel(const int* __restrict__ ei, int E, int Etot) {
    int idx = blockIdx.x * blockDim.x + threadIdx.x;
    if (idx >= Etot) return;
    int dst = (idx < E) ? ei[E + idx] : (idx - E);
    int slot = atomicAdd(&g_deg[dst], 1);
    g_eslot[idx] = slot;
}

__global__ void scan1_kernel(int N) {
    __shared__ int sh[SCAN_CHUNK];
    int t = threadIdx.x;
    int i = blockIdx.x * SCAN_CHUNK + t;
    sh[t] = (i < N) ? g_deg[i] : 0;
    __syncthreads();
#pragma unroll
    for (int s = SCAN_CHUNK / 2; s > 0; s >>= 1) {
        if (t < s) sh[t] += sh[t + s];
        __syncthreads();
    }
    if (t == 0) g_csum[blockIdx.x] = sh[0];
}

// fused: every block redundantly exclusive-scans the chunk sums, then does its chunk
__global__ void scan3_fused_kernel(int N, int Etot, int nch) {
    __shared__ int chs[NCHMAX];
    __shared__ int sh[SCAN_CHUNK];
    int t = threadIdx.x;
    if (t < NCHMAX) chs[t] = (t < nch) ? g_csum[t] : 0;
    __syncthreads();
#pragma unroll
    for (int off = 1; off < NCHMAX; off <<= 1) {
        int add = 0;
        if (t < NCHMAX && t >= off) add = chs[t - off];
        __syncthreads();
        if (t < NCHMAX) chs[t] += add;
        __syncthreads();
    }
    int boff = (blockIdx.x == 0) ? 0 : chs[blockIdx.x - 1];
    int i = blockIdx.x * SCAN_CHUNK + t;
    int v = (i < N) ? g_deg[i] : 0;
    sh[t] = v;
    __syncthreads();
#pragma unroll
    for (int off = 1; off < SCAN_CHUNK; off <<= 1) {
        int add = (t >= off) ? sh[t - off] : 0;
        __syncthreads();
        sh[t] += add;
        __syncthreads();
    }
    if (i < N) g_rowstart[i] = sh[t] - v + boff;
    if (blockIdx.x == 0 && t == 0) g_rowstart[N] = Etot;
}

__global__ void fill_kernel(const int* __restrict__ ei, int E, int Etot) {
    int idx = blockIdx.x * blockDim.x + threadIdx.x;
    if (idx >= Etot) return;
    int src, dst;
    if (idx < E) { src = ei[idx]; dst = ei[E + idx]; } else { src = dst = idx - E; }
    g_srcs[g_rowstart[dst] + g_eslot[idx]] = src;
}

// ---------------- layer1 GEMM (tf32 tensor cores) + fused alpha epilogue ----------------
__global__ __launch_bounds__(512) void gemm1_kernel(
    const float* __restrict__ x, const float* __restrict__ W,
    const float* __restrict__ asrc, const float* __restrict__ adst, int N) {
    extern __shared__ float sm[];
    float* xs = sm;               // 256*132
    float* wk = sm + 256 * 132;   // 128*136
    int tid = threadIdx.x;
    int base = blockIdx.x * 256;

    for (int i = tid; i < 4096; i += 512) {
        int k = i >> 5, c4 = i & 31;
        float4 v = ((const float4*)W)[i];
        float4 o;
        o.x = __uint_as_float(f2tf32(v.x));
        o.y = __uint_as_float(f2tf32(v.y));
        o.z = __uint_as_float(f2tf32(v.z));
        o.w = __uint_as_float(f2tf32(v.w));
        *(float4*)&wk[k * 136 + c4 * 4] = o;
    }
    for (int i = tid; i < 8192; i += 512) {
        int r = i >> 5, c4 = i & 31;
        int gr = base + r;
        float4 v = make_float4(0.f, 0.f, 0.f, 0.f);
        if (gr < N) v = ((const float4*)x)[gr * 32 + c4];
        float4 o;
        o.x = __uint_as_float(f2tf32(v.x));
        o.y = __uint_as_float(f2tf32(v.y));
        o.z = __uint_as_float(f2tf32(v.z));
        o.w = __uint_as_float(f2tf32(v.w));
        *(float4*)&xs[r * 132 + c4 * 4] = o;
    }
    __syncthreads();

    int w = tid >> 5, lane = tid & 31;
    int tg = lane & 3, grp = lane >> 2;
    int r0 = w * 16;

    float acc[16][4];
#pragma unroll
    for (int j = 0; j < 16; j++)
#pragma unroll
        for (int q = 0; q < 4; q++) acc[j][q] = 0.f;

#pragma unroll 4
    for (int ks = 0; ks < 16; ks++) {
        int k0 = ks * 8;
        const float* ax = xs + (r0 + grp) * 132 + k0 + tg;
        uint32_t a0 = __float_as_uint(ax[0]);
        uint32_t a1 = __float_as_uint(ax[8 * 132]);
        uint32_t a2 = __float_as_uint(ax[4]);
        uint32_t a3 = __float_as_uint(ax[8 * 132 + 4]);
        const float* bx = wk + (k0 + tg) * 136 + grp;
#pragma unroll
        for (int j = 0; j < 16; j++) {
            uint32_t b0 = __float_as_uint(bx[8 * j]);
            uint32_t b1 = __float_as_uint(bx[4 * 136 + 8 * j]);
            mma_tf32(acc[j][0], acc[j][1], acc[j][2], acc[j][3], a0, a1, a2, a3, b0, b1);
        }
    }

    // ---- epilogue: store h1 (bf16) + fused alpha dot products ----
    int gr0 = base + r0 + grp;
    int gr8 = gr0 + 8;
    float s_r0[4] = {0, 0, 0, 0}, s_r8[4] = {0, 0, 0, 0};
    float d_r0[4] = {0, 0, 0, 0}, d_r8[4] = {0, 0, 0, 0};
#pragma unroll
    for (int j = 0; j < 16; j++) {
        int c = 8 * j + 2 * tg;
        int h = j >> 2;
        float A0 = __ldg(&asrc[c]), A1 = __ldg(&asrc[c + 1]);
        float D0 = __ldg(&adst[c]), D1 = __ldg(&adst[c + 1]);
        s_r0[h] = fmaf(acc[j][0], A0, fmaf(acc[j][1], A1, s_r0[h]));
        s_r8[h] = fmaf(acc[j][2], A0, fmaf(acc[j][3], A1, s_r8[h]));
        d_r0[h] = fmaf(acc[j][0], D0, fmaf(acc[j][1], D1, d_r0[h]));
        d_r8[h] = fmaf(acc[j][2], D0, fmaf(acc[j][3], D1, d_r8[h]));
        if (gr0 < N)
            *(__nv_bfloat162*)&g_h1b[(size_t)gr0 * 128 + c] =
                __float22bfloat162_rn(make_float2(acc[j][0], acc[j][1]));
        if (gr8 < N)
            *(__nv_bfloat162*)&g_h1b[(size_t)gr8 * 128 + c] =
                __float22bfloat162_rn(make_float2(acc[j][2], acc[j][3]));
    }
#pragma unroll
    for (int h = 0; h < 4; h++) {
        s_r0[h] += __shfl_xor_sync(0xffffffffu, s_r0[h], 1);
        s_r0[h] += __shfl_xor_sync(0xffffffffu, s_r0[h], 2);
        s_r8[h] += __shfl_xor_sync(0xffffffffu, s_r8[h], 1);
        s_r8[h] += __shfl_xor_sync(0xffffffffu, s_r8[h], 2);
        d_r0[h] += __shfl_xor_sync(0xffffffffu, d_r0[h], 1);
        d_r0[h] += __shfl_xor_sync(0xffffffffu, d_r0[h], 2);
        d_r8[h] += __shfl_xor_sync(0xffffffffu, d_r8[h], 1);
        d_r8[h] += __shfl_xor_sync(0xffffffffu, d_r8[h], 2);
    }
    if (tg == 0) {
        if (gr0 < N) {
            g_as1[gr0] = make_float4(s_r0[0], s_r0[1], s_r0[2], s_r0[3]);
            g_ad1[gr0] = make_float4(d_r0[0], d_r0[1], d_r0[2], d_r0[3]);
        }
        if (gr8 < N) {
            g_as1[gr8] = make_float4(s_r8[0], s_r8[1], s_r8[2], s_r8[3]);
            g_ad1[gr8] = make_float4(d_r8[0], d_r8[1], d_r8[2], d_r8[3]);
        }
    }
}

// ---------------- layer1 fused softmax + aggregation: warp per dst ----------------
// NOTE: softmax computed WITHOUT max subtraction (shift-invariant; scores bounded ~±15,
// far from fp32 exp overflow at ±88).
__global__ void agg1_kernel(int N) {
    __shared__ float4 swsel[8][32];   // per-warp: per-edge weights (w0..w3)
    __shared__ int    sssrc[8][32];   // per-warp: per-edge src ids
    int gw = (blockIdx.x * blockDim.x + threadIdx.x) >> 5;
    int lane = threadIdx.x & 31;
    int wip = (threadIdx.x >> 5) & 7;
    if (gw >= N) return;
    int row = g_rowstart[gw], end = g_rowstart[gw + 1];
    int deg = end - row;
    float4 d4 = g_ad1[gw];

    if (deg <= 32) {
        // ---- fast path: no-max softmax, weights staged in smem, 2 edges/iter ----
        int msrc = 0;
        float t0 = 0.f, t1 = 0.f, t2 = 0.f, t3 = 0.f;
        if (lane < deg) {
            msrc = __ldg(&g_srcs[row + lane]);
            float4 a = g_as1[msrc];
            t0 = __expf(lrelu(a.x + d4.x));
            t1 = __expf(lrelu(a.y + d4.y));
            t2 = __expf(lrelu(a.z + d4.z));
            t3 = __expf(lrelu(a.w + d4.w));
        }
        float w0 = t0 / wsumf(t0);
        float w1 = t1 / wsumf(t1);
        float w2 = t2 / wsumf(t2);
        float w3 = t3 / wsumf(t3);
        swsel[wip][lane] = make_float4(w0, w1, w2, w3);
        sssrc[wip][lane] = msrc;
        __syncwarp();

        int half = lane >> 4;
        int hl = lane & 15;
        int head = hl >> 2;
        const float* wselp = (const float*)&swsel[wip][0];
        float a8[8];
#pragma unroll
        for (int j = 0; j < 8; j++) a8[j] = 0.f;

#pragma unroll 4
        for (int e = 0; e < deg; e += 2) {
            int idx = e + half;
            int   src = sssrc[wip][idx];
            float ws  = wselp[idx * 4 + head];
            uint4 hv = *(const uint4*)(g_h1b + (size_t)src * 128 + hl * 8);
            float2 f0 = __bfloat1622float2(*(__nv_bfloat162*)&hv.x);
            float2 f1 = __bfloat1622float2(*(__nv_bfloat162*)&hv.y);
            float2 f2 = __bfloat1622float2(*(__nv_bfloat162*)&hv.z);
            float2 f3 = __bfloat1622float2(*(__nv_bfloat162*)&hv.w);
            a8[0] = fmaf(ws, f0.x, a8[0]); a8[1] = fmaf(ws, f0.y, a8[1]);
            a8[2] = fmaf(ws, f1.x, a8[2]); a8[3] = fmaf(ws, f1.y, a8[3]);
            a8[4] = fmaf(ws, f2.x, a8[4]); a8[5] = fmaf(ws, f2.y, a8[5]);
            a8[6] = fmaf(ws, f3.x, a8[6]); a8[7] = fmaf(ws, f3.y, a8[7]);
        }
#pragma unroll
        for (int j = 0; j < 8; j++) a8[j] += __shfl_xor_sync(0xffffffffu, a8[j], 16);
        if (half == 0) {
            __nv_bfloat162 q0 = __float22bfloat162_rn(make_float2(a8[0], a8[1]));
            __nv_bfloat162 q1 = __float22bfloat162_rn(make_float2(a8[2], a8[3]));
            __nv_bfloat162 q2 = __float22bfloat162_rn(make_float2(a8[4], a8[5]));
            __nv_bfloat162 q3 = __float22bfloat162_rn(make_float2(a8[6], a8[7]));
            uint4 ov;
            ov.x = *(uint32_t*)&q0; ov.y = *(uint32_t*)&q1;
            ov.z = *(uint32_t*)&q2; ov.w = *(uint32_t*)&q3;
            *(uint4*)(g_out1b + (size_t)gw * 128 + hl * 8) = ov;
        }
    } else {
        // ---- slow path (rare): no-max softmax, 2 passes ----
        float4 acc = make_float4(0.f, 0.f, 0.f, 0.f);
        float s0 = 0.f, s1 = 0.f, s2 = 0.f, s3 = 0.f;
        for (int j = row + lane; j < end; j += 32) {
            int src = __ldg(&g_srcs[j]);
            float4 a = g_as1[src];
            s0 += __expf(lrelu(a.x + d4.x));
            s1 += __expf(lrelu(a.y + d4.y));
            s2 += __expf(lrelu(a.z + d4.z));
            s3 += __expf(lrelu(a.w + d4.w));
        }
        float i0 = 1.f / wsumf(s0);
        float i1 = 1.f / wsumf(s1);
        float i2 = 1.f / wsumf(s2);
        float i3 = 1.f / wsumf(s3);
        for (int cb = row; cb < end; cb += 32) {
            int rem = end - cb;
            int msrc = 0;
            float w0 = 0.f, w1 = 0.f, w2 = 0.f, w3 = 0.f;
            if (lane < rem) {
                msrc = __ldg(&g_srcs[cb + lane]);
                float4 a = g_as1[msrc];
                w0 = __expf(lrelu(a.x + d4.x)) * i0;
                w1 = __expf(lrelu(a.y + d4.y)) * i1;
                w2 = __expf(lrelu(a.z + d4.z)) * i2;
                w3 = __expf(lrelu(a.w + d4.w)) * i3;
            }
            int cnt = rem < 32 ? rem : 32;
            for (int e = 0; e < cnt; e++) {
                int   src = __shfl_sync(0xffffffffu, msrc, e);
                float b0  = __shfl_sync(0xffffffffu, w0, e);
                float b1v = __shfl_sync(0xffffffffu, w1, e);
                float b2v = __shfl_sync(0xffffffffu, w2, e);
                float b3  = __shfl_sync(0xffffffffu, w3, e);
                float wl = (lane & 8) ? b1v : b0;
                float wh = (lane & 8) ? b3 : b2v;
                float ws = (lane & 16) ? wh : wl;
                uint2 hv = *(const uint2*)(g_h1b + (size_t)src * 128 + lane * 4);
                float2 f0 = __bfloat1622float2(*(__nv_bfloat162*)&hv.x);
                float2 f1 = __bfloat1622float2(*(__nv_bfloat162*)&hv.y);
                acc.x = fmaf(ws, f0.x, acc.x);
                acc.y = fmaf(ws, f0.y, acc.y);
                acc.z = fmaf(ws, f1.x, acc.z);
                acc.w = fmaf(ws, f1.y, acc.w);
            }
        }
        __nv_bfloat162 o0 = __float22bfloat162_rn(make_float2(acc.x, acc.y));
        __nv_bfloat162 o1 = __float22bfloat162_rn(make_float2(acc.z, acc.w));
        uint2 ov;
        ov.x = *(uint32_t*)&o0;
        ov.y = *(uint32_t*)&o1;
        *(uint2*)(g_out1b + (size_t)gw * 128 + lane * 4) = ov;
    }
}

// ---------------- layer2: h2 = elu(out1+b1) @ W2, plus attention scores ----------------
__global__ void layer2_kernel(const float* __restrict__ W2, const float* __restrict__ b1,
                              const float* __restrict__ asrc2, const float* __restrict__ adst2, int N) {
    __shared__ float w2s[128 * 8];
    __shared__ float b1s[128];
    __shared__ float s2s[8], d2s[8];
    int tid = threadIdx.x;
    for (int i = tid; i < 1024; i += 256) w2s[i] = W2[i];
    if (tid < 128) b1s[tid] = b1[tid];
    if (tid < 8) { s2s[tid] = asrc2[tid]; d2s[tid] = adst2[tid]; }
    __syncthreads();
    int n = blockIdx.x * 256 + tid;
    if (n >= N) return;
    float acc[8];
#pragma unroll
    for (int c = 0; c < 8; c++) acc[c] = 0.f;
    const uint4* op = (const uint4*)&g_out1b[(size_t)n * 128];
#pragma unroll 4
    for (int k8 = 0; k8 < 16; k8++) {
        uint4 v = op[k8];
        float2 f0 = __bfloat1622float2(*(__nv_bfloat162*)&v.x);
        float2 f1 = __bfloat1622float2(*(__nv_bfloat162*)&v.y);
        float2 f2 = __bfloat1622float2(*(__nv_bfloat162*)&v.z);
        float2 f3 = __bfloat1622float2(*(__nv_bfloat162*)&v.w);
        float vv[8] = {f0.x, f0.y, f1.x, f1.y, f2.x, f2.y, f3.x, f3.y};
#pragma unroll
        for (int j = 0; j < 8; j++) {
            int k = k8 * 8 + j;
            float tv = eluf(vv[j] + b1s[k]);
#pragma unroll
            for (int c = 0; c < 8; c++) acc[c] = fmaf(tv, w2s[k * 8 + c], acc[c]);
        }
    }
    ((float4*)&g_h2[n * 8])[0] = make_float4(acc[0], acc[1], acc[2], acc[3]);
    ((float4*)&g_h2[n * 8])[1] = make_float4(acc[4], acc[5], acc[6], acc[7]);
    float s = 0.f, d = 0.f;
#pragma unroll
    for (int c = 0; c < 8; c++) { s += acc[c] * s2s[c]; d += acc[c] * d2s[c]; }
    g_as2[n] = s;
    g_ad2[n] = d;
}

// ---------------- layer2 softmax + aggregation + final output (fused) ----------------
// fast path: 8 edge-groups x 4 channel-pairs lane layout; no-max softmax.
__global__ void agg2_final_kernel(const float* __restrict__ b2, const float* __restrict__ Wlin,
                                  const float* __restrict__ blin, float* __restrict__ out, int N) {
    __shared__ float sws2[8][32];
    __shared__ int   ssrc2[8][32];
    int gw = (blockIdx.x * blockDim.x + threadIdx.x) >> 5;
    int lane = threadIdx.x & 31;
    int wip = (threadIdx.x >> 5) & 7;
    if (gw >= N) return;
    int row = g_rowstart[gw], end = g_rowstart[gw + 1];
    int deg = end - row;
    float dd = g_ad2[gw];

    if (deg <= 32) {
        int msrc = 0;
        float t = 0.f;
        if (lane < deg) {
            msrc = __ldg(&g_srcs[row + lane]);
            t = __expf(lrelu(g_as2[msrc] + dd));
        }
        float w = t / wsumf(t);
        sws2[wip][lane] = w;
        ssrc2[wip][lane] = msrc;
        __syncwarp();

        int eg = lane >> 2;        // edge group 0..7
        int cg = lane & 3;         // channel pair 0..3 -> channels 2cg, 2cg+1
        float p0 = 0.f, p1 = 0.f;
#pragma unroll
        for (int q = 0; q < 4; q++) {
            int e = eg + q * 8;
            if (e < deg) {
                int   src = ssrc2[wip][e];
                float ww  = sws2[wip][e];
                float2 hv = *(const float2*)(g_h2 + (size_t)src * 8 + cg * 2);
                p0 = fmaf(ww, hv.x, p0);
                p1 = fmaf(ww, hv.y, p1);
            }
        }
        // reduce across edge groups (lanes sharing cg): xor 4, 8, 16
#pragma unroll
        for (int o = 4; o <= 16; o <<= 1) {
            p0 += __shfl_xor_sync(0xffffffffu, p0, o);
            p1 += __shfl_xor_sync(0xffffffffu, p1, o);
        }
        // lanes 0..3 now hold channel pairs; compute final scalar via quad reduce
        float y0 = eluf(p0 + __ldg(&b2[cg * 2]))     * __ldg(&Wlin[cg * 2]);
        float y1 = eluf(p1 + __ldg(&b2[cg * 2 + 1])) * __ldg(&Wlin[cg * 2 + 1]);
        float y = y0 + y1;
        y += __shfl_xor_sync(0xffffffffu, y, 1);
        y += __shfl_xor_sync(0xffffffffu, y, 2);
        if (lane == 0)
            out[gw] = 1.f / (1.f + __expf(-(y + __ldg(&blin[0]))));
    } else {
        float s = 0.f;
        for (int j = row + lane; j < end; j += 32) {
            int src = __ldg(&g_srcs[j]);
            s += __expf(lrelu(g_as2[src] + dd));
        }
        float inv = 1.f / wsumf(s);
        float a0 = 0.f, a1 = 0.f, a2 = 0.f, a3 = 0.f, a4 = 0.f, a5 = 0.f, a6 = 0.f, a7 = 0.f;
        for (int j = row + lane; j < end; j += 32) {
            int src = __ldg(&g_srcs[j]);
            float w = __expf(lrelu(g_as2[src] + dd)) * inv;
            const float4* hp = (const float4*)(g_h2 + (size_t)src * 8);
            float4 v0 = hp[0], v1 = hp[1];
            a0 = fmaf(w, v0.x, a0); a1 = fmaf(w, v0.y, a1);
            a2 = fmaf(w, v0.z, a2); a3 = fmaf(w, v0.w, a3);
            a4 = fmaf(w, v1.x, a4); a5 = fmaf(w, v1.y, a5);
            a6 = fmaf(w, v1.z, a6); a7 = fmaf(w, v1.w, a7);
        }
        a0 = wsumf(a0); a1 = wsumf(a1); a2 = wsumf(a2); a3 = wsumf(a3);
        a4 = wsumf(a4); a5 = wsumf(a5); a6 = wsumf(a6); a7 = wsumf(a7);
        if (lane == 0) {
            float o[8] = {a0, a1, a2, a3, a4, a5, a6, a7};
            float y = __ldg(&blin[0]);
#pragma unroll
            for (int j = 0; j < 8; j++) {
                float t = eluf(o[j] + __ldg(&b2[j]));
                y = fmaf(t, __ldg(&Wlin[j]), y);
            }
            out[gw] = 1.f / (1.f + __expf(-y));
        }
    }
}

// ---------------- launch ----------------
extern "C" void kernel_launch(void* const* d_in, const int* in_sizes, int n_in,
                              void* d_out, int out_size) {
    const float* x    = (const float*)d_in[0];
    const int*   ei   = (const int*)d_in[1];
    // d_in[2] edge_attr unused
    const float* W1   = (const float*)d_in[3];
    const float* as1  = (const float*)d_in[4];
    const float* ad1  = (const float*)d_in[5];
    const float* b1   = (const float*)d_in[6];
    const float* W2   = (const float*)d_in[7];
    const float* as2w = (const float*)d_in[8];
    const float* ad2w = (const float*)d_in[9];
    const float* b2   = (const float*)d_in[10];
    const float* Wlin = (const float*)d_in[11];
    const float* blin = (const float*)d_in[12];
    float* out = (float*)d_out;

    int N = in_sizes[0] / 128;
    int E = in_sizes[1] / 2;
    int Etot = E + N;
    int nch = (N + SCAN_CHUNK - 1) / SCAN_CHUNK;
    const int TB = 256;
    const int SMEM_GEMM = (256 * 132 + 128 * 136) * 4;

    cudaFuncSetAttribute(gemm1_kernel, cudaFuncAttributeMaxDynamicSharedMemorySize, SMEM_GEMM);

    // Fork: CSR build (ei only) concurrent with gemm1 (x/W1 only).
    cudaStream_t s2;
    cudaStreamCreate(&s2);
    cudaEvent_t evFork, evJoin;
    cudaEventCreateWithFlags(&evFork, cudaEventDisableTiming);
    cudaEventCreateWithFlags(&evJoin, cudaEventDisableTiming);

    cudaEventRecord(evFork, 0);
    cudaStreamWaitEvent(s2, evFork, 0);

    zero_deg_kernel<<<(N + TB - 1) / TB, TB, 0, s2>>>(N);
    count_kernel<<<(Etot + TB - 1) / TB, TB, 0, s2>>>(ei, E, Etot);
    scan1_kernel<<<nch, SCAN_CHUNK, 0, s2>>>(N);
    scan3_fused_kernel<<<nch, SCAN_CHUNK, 0, s2>>>(N, Etot, nch);
    fill_kernel<<<(Etot + TB - 1) / TB, TB, 0, s2>>>(ei, E, Etot);
    cudaEventRecord(evJoin, s2);

    gemm1_kernel<<<(N + 255) / 256, 512, SMEM_GEMM>>>(x, W1, as1, ad1, N);

    cudaStreamWaitEvent(0, evJoin, 0);
    agg1_kernel<<<(N * 32 + TB - 1) / TB, TB>>>(N);
    layer2_kernel<<<(N + TB - 1) / TB, TB>>>(W2, b1, as2w, ad2w, N);
    agg2_final_kernel<<<(N * 32 + TB - 1) / TB, TB>>>(b2, Wlin, blin, out, N);

    cudaEventDestroy(evFork);
    cudaEventDestroy(evJoin);
    cudaStreamDestroy(s2);
}